// round 1
// baseline (speedup 1.0000x reference)
#include <cuda_runtime.h>
#include <math.h>

#define BB 8
#define CC 64
#define HH 128
#define WW 128
#define HW (HH*WW)
#define KK 9
#define CO 64
#define CK (CC*KK)   // 576

// Scratch (device globals; no runtime allocation allowed)
__device__ float g_xt[BB*HW*CC];      // x transposed to NHWC  (33.5 MB)
__device__ float g_off[BB*HW*KK*3];   // per (pixel,tap): py,px,mask (14.2 MB)
__device__ float g_wt[CK*CO];         // reordered dcn weight [j=t*64+c][co]

// ---------------------------------------------------------------------------
// Kernel A: NCHW -> NHWC transpose (per batch it's a [C][P] -> [P][C] transpose)
// ---------------------------------------------------------------------------
__global__ void k_transpose(const float* __restrict__ x) {
    __shared__ float tile[32][33];
    int b  = blockIdx.z;
    int p0 = blockIdx.x * 32;
    int c0 = blockIdx.y * 32;
    int tx = threadIdx.x, ty = threadIdx.y;   // 32 x 8
    const float* xb = x + (size_t)b * CC * HW;
    #pragma unroll
    for (int i = 0; i < 32; i += 8)
        tile[ty + i][tx] = xb[(size_t)(c0 + ty + i) * HW + p0 + tx];
    __syncthreads();
    float* xo = g_xt + (size_t)b * HW * CC;
    #pragma unroll
    for (int i = 0; i < 32; i += 8)
        xo[(size_t)(p0 + ty + i) * CC + c0 + tx] = tile[tx][ty + i];
}

// ---------------------------------------------------------------------------
// Kernel W: reorder w_dcn [co][c][ky][kx] -> g_wt[(t*64+c)][co]
// ---------------------------------------------------------------------------
__global__ void k_wreorder(const float* __restrict__ wd) {
    int idx = blockIdx.x * 256 + threadIdx.x;
    if (idx < CK * CO) {
        int j = idx >> 6, co = idx & 63;
        int t = j >> 6, c = j & 63;
        g_wt[idx] = wd[co * CK + c * KK + t];
    }
}

// ---------------------------------------------------------------------------
// Kernel B: offset conv (3x3, 64->27) + sampling coord / sigmoid mask
// One thread per output pixel, 128 threads = one output row (coalesced NCHW reads).
// Weights in smem reordered to [ct=c*9+t][o padded to 28] for float4 broadcast.
// ---------------------------------------------------------------------------
__global__ void k_offset(const float* __restrict__ x,
                         const float* __restrict__ w_off,
                         const float* __restrict__ b_off) {
    extern __shared__ float wsr[];            // [576][28]
    int tid = threadIdx.x;                    // 128
    for (int i = tid; i < CK; i += 128) wsr[i * 28 + 27] = 0.f;
    for (int i = tid; i < 27 * CK; i += 128) {
        int o  = i / CK;
        int ct = i - o * CK;                  // c*9 + t
        wsr[ct * 28 + o] = w_off[i];
    }
    __syncthreads();

    int p  = blockIdx.x * 128 + tid;
    int b  = blockIdx.y;
    int ho = p >> 7, wo = p & 127;

    float acc[28];
    #pragma unroll
    for (int o = 0; o < 27; o++) acc[o] = b_off[o];
    acc[27] = 0.f;

    const float* xb = x + (size_t)b * CC * HW;
    #pragma unroll
    for (int t = 0; t < 9; t++) {
        int y  = ho + (t / 3) - 1;
        int xx = wo + (t % 3) - 1;
        if (y < 0 || y >= HH || xx < 0 || xx >= WW) continue;   // zero padding
        const float* xp = xb + y * WW + xx;
        #pragma unroll 4
        for (int c = 0; c < CC; c++) {
            float xv = xp[(size_t)c * HW];
            const float4* wr = (const float4*)&wsr[(c * 9 + t) * 28];
            #pragma unroll
            for (int q = 0; q < 7; q++) {
                float4 w4 = wr[q];
                acc[q * 4 + 0] += xv * w4.x;
                acc[q * 4 + 1] += xv * w4.y;
                acc[q * 4 + 2] += xv * w4.z;
                acc[q * 4 + 3] += xv * w4.w;
            }
        }
    }

    float* op = g_off + ((size_t)(b * HW + p)) * (KK * 3);
    #pragma unroll
    for (int t = 0; t < 9; t++) {
        float py = acc[t]     + (float)(ho - 1 + t / 3);
        float px = acc[9 + t] + (float)(wo - 1 + t % 3);
        float mm = 1.f / (1.f + expf(-acc[18 + t]));
        op[t * 3 + 0] = py;
        op[t * 3 + 1] = px;
        op[t * 3 + 2] = mm;
    }
}

// ---------------------------------------------------------------------------
// Kernel C: fused bilinear gather (+mask) into smem col, then GEMM with w_dcn.
// 256 threads, TILE=32 pixels per block.
//   Phase A: 8-lane groups per (pixel,tap): 4 corners x 2 float4 coalesced reads
//            from NHWC x; col[pix][t*64+c] = mask * bilinear.
//   Phase B: 9 weight chunks [64c][64co] (16KB) staged in smem;
//            thread = (pixel, 8 consecutive co) with 8 fp32 accumulators.
// ---------------------------------------------------------------------------
#define TILE 32
#define COLSTRIDE 580          // 580 % 4 == 0 (16B align), 580 % 32 == 4 (no bank conflicts)

__global__ void k_dcn(const float* __restrict__ b_dcn, float* __restrict__ out) {
    extern __shared__ float sm[];
    float* col = sm;                       // TILE * COLSTRIDE
    float* ws  = sm + TILE * COLSTRIDE;    // 64 * 64

    int tid = threadIdx.x;                 // 256
    int b   = blockIdx.y;
    int p0  = blockIdx.x * TILE;

    // ---- Phase A: build col ----
    int g     = tid >> 3;                  // 32 groups
    int lane  = tid & 7;
    int cbase = lane * 8;
    const float* xb = g_xt + (size_t)b * HW * CC;

    #pragma unroll
    for (int it = 0; it < 9; it++) {
        int item = it * 32 + g;            // 0..287 = pixel*9 + t
        int pi   = item / 9;
        int t    = item - pi * 9;
        int p    = p0 + pi;

        const float* op = g_off + ((size_t)(b * HW + p)) * 27 + t * 3;
        float py = op[0], px = op[1], mm = op[2];
        float y0f = floorf(py), x0f = floorf(px);
        float dy = py - y0f, dx = px - x0f;
        int y0 = (int)y0f, x0 = (int)x0f;
        int y1 = y0 + 1,  x1 = x0 + 1;
        bool vy0 = (y0 >= 0) & (y0 < HH);
        bool vy1 = (y1 >= 0) & (y1 < HH);
        bool vx0 = (x0 >= 0) & (x0 < WW);
        bool vx1 = (x1 >= 0) & (x1 < WW);
        float w00 = (1.f - dy) * (1.f - dx) * mm;
        float w01 = (1.f - dy) * dx * mm;
        float w10 = dy * (1.f - dx) * mm;
        float w11 = dy * dx * mm;

        float r0x = 0.f, r0y = 0.f, r0z = 0.f, r0w = 0.f;
        float r1x = 0.f, r1y = 0.f, r1z = 0.f, r1w = 0.f;

        if (vy0 & vx0) {
            const float4* pp = (const float4*)(xb + ((size_t)y0 * WW + x0) * CC + cbase);
            float4 v = pp[0];
            r0x += w00 * v.x; r0y += w00 * v.y; r0z += w00 * v.z; r0w += w00 * v.w;
            v = pp[1];
            r1x += w00 * v.x; r1y += w00 * v.y; r1z += w00 * v.z; r1w += w00 * v.w;
        }
        if (vy0 & vx1) {
            const float4* pp = (const float4*)(xb + ((size_t)y0 * WW + x1) * CC + cbase);
            float4 v = pp[0];
            r0x += w01 * v.x; r0y += w01 * v.y; r0z += w01 * v.z; r0w += w01 * v.w;
            v = pp[1];
            r1x += w01 * v.x; r1y += w01 * v.y; r1z += w01 * v.z; r1w += w01 * v.w;
        }
        if (vy1 & vx0) {
            const float4* pp = (const float4*)(xb + ((size_t)y1 * WW + x0) * CC + cbase);
            float4 v = pp[0];
            r0x += w10 * v.x; r0y += w10 * v.y; r0z += w10 * v.z; r0w += w10 * v.w;
            v = pp[1];
            r1x += w10 * v.x; r1y += w10 * v.y; r1z += w10 * v.z; r1w += w10 * v.w;
        }
        if (vy1 & vx1) {
            const float4* pp = (const float4*)(xb + ((size_t)y1 * WW + x1) * CC + cbase);
            float4 v = pp[0];
            r0x += w11 * v.x; r0y += w11 * v.y; r0z += w11 * v.z; r0w += w11 * v.w;
            v = pp[1];
            r1x += w11 * v.x; r1y += w11 * v.y; r1z += w11 * v.z; r1w += w11 * v.w;
        }

        float* cdst = &col[pi * COLSTRIDE + t * 64 + cbase];
        ((float4*)cdst)[0] = make_float4(r0x, r0y, r0z, r0w);
        ((float4*)cdst)[1] = make_float4(r1x, r1y, r1z, r1w);
    }
    __syncthreads();

    // ---- Phase B: GEMM col[32][576] x wt[576][64] ----
    int pix = tid >> 3;
    int cog = (tid & 7) * 8;
    float acc[8];
    #pragma unroll
    for (int i = 0; i < 8; i++) acc[i] = 0.f;

    for (int kk = 0; kk < 9; kk++) {
        const float4* wsrc = (const float4*)(g_wt + kk * 64 * 64);
        #pragma unroll
        for (int i = tid; i < 1024; i += 256)
            ((float4*)ws)[i] = wsrc[i];
        __syncthreads();

        const float* crow = &col[pix * COLSTRIDE + kk * 64];
        #pragma unroll 8
        for (int c = 0; c < 64; c++) {
            float cv = crow[c];
            const float4* w4 = (const float4*)&ws[c * 64 + cog];
            float4 a = w4[0], bb4 = w4[1];
            acc[0] += cv * a.x;  acc[1] += cv * a.y;
            acc[2] += cv * a.z;  acc[3] += cv * a.w;
            acc[4] += cv * bb4.x; acc[5] += cv * bb4.y;
            acc[6] += cv * bb4.z; acc[7] += cv * bb4.w;
        }
        __syncthreads();
    }

    int p = p0 + pix;
    float* ob = out + (size_t)b * CO * HW;
    #pragma unroll
    for (int i = 0; i < 8; i++) {
        int co = cog + i;
        ob[(size_t)co * HW + p] = acc[i] + b_dcn[co];
    }
}

// ---------------------------------------------------------------------------
extern "C" void kernel_launch(void* const* d_in, const int* in_sizes, int n_in,
                              void* d_out, int out_size) {
    const float* x        = (const float*)d_in[0];
    const float* w_offset = (const float*)d_in[1];
    const float* b_offset = (const float*)d_in[2];
    const float* w_dcn    = (const float*)d_in[3];
    const float* b_dcn    = (const float*)d_in[4];
    float* out = (float*)d_out;

    const int SMEM_B = CK * 28 * 4;                          // 64512
    const int SMEM_C = (TILE * COLSTRIDE + 64 * 64) * 4;     // 90624
    cudaFuncSetAttribute(k_offset, cudaFuncAttributeMaxDynamicSharedMemorySize, SMEM_B);
    cudaFuncSetAttribute(k_dcn,    cudaFuncAttributeMaxDynamicSharedMemorySize, SMEM_C);

    k_transpose<<<dim3(HW / 32, CC / 32, BB), dim3(32, 8)>>>(x);
    k_wreorder<<<(CK * CO + 255) / 256, 256>>>(w_dcn);
    k_offset<<<dim3(HW / 128, BB), 128, SMEM_B>>>(x, w_offset, b_offset);
    k_dcn<<<dim3(HW / TILE, BB), 256, SMEM_C>>>(b_dcn, out);
}

// round 2
// speedup vs baseline: 2.9917x; 2.9917x over previous
#include <cuda_runtime.h>
#include <math.h>

#define BB 8
#define CC 64
#define HH 128
#define WW 128
#define HW (HH*WW)
#define KK 9
#define CO 64
#define CK (CC*KK)   // 576

typedef unsigned long long u64;

__device__ float g_xt[BB*HW*CC];      // x transposed to NHWC
__device__ float g_off[BB*HW*KK*3];   // per (pixel,tap): py,px,mask
__device__ float g_wt[CK*CO];         // reordered dcn weight [(t*64+c)][co]

__device__ __forceinline__ u64 pk2(float lo, float hi) {
    u64 r; asm("mov.b64 %0,{%1,%2};" : "=l"(r) : "f"(lo), "f"(hi)); return r;
}
__device__ __forceinline__ void fma2(u64 &d, u64 a, u64 b) {
    asm("fma.rn.f32x2 %0,%1,%2,%0;" : "+l"(d) : "l"(a), "l"(b));
}
__device__ __forceinline__ void up2(u64 v, float &a, float &b) {
    asm("mov.b64 {%0,%1},%2;" : "=f"(a), "=f"(b) : "l"(v));
}

// ---------------------------------------------------------------------------
// Kernel A: NCHW -> NHWC transpose
// ---------------------------------------------------------------------------
__global__ void k_transpose(const float* __restrict__ x) {
    __shared__ float tile[32][33];
    int b  = blockIdx.z;
    int p0 = blockIdx.x * 32;
    int c0 = blockIdx.y * 32;
    int tx = threadIdx.x, ty = threadIdx.y;   // 32 x 8
    const float* xb = x + (size_t)b * CC * HW;
    #pragma unroll
    for (int i = 0; i < 32; i += 8)
        tile[ty + i][tx] = xb[(size_t)(c0 + ty + i) * HW + p0 + tx];
    __syncthreads();
    float* xo = g_xt + (size_t)b * HW * CC;
    #pragma unroll
    for (int i = 0; i < 32; i += 8)
        xo[(size_t)(p0 + ty + i) * CC + c0 + tx] = tile[tx][ty + i];
}

// ---------------------------------------------------------------------------
// Kernel W: reorder w_dcn [co][c][t] -> g_wt[(t*64+c)][co]
// ---------------------------------------------------------------------------
__global__ void k_wreorder(const float* __restrict__ wd) {
    int idx = blockIdx.x * 256 + threadIdx.x;
    if (idx < CK * CO) {
        int j = idx >> 6, co = idx & 63;
        int t = j >> 6, c = j & 63;
        g_wt[idx] = wd[co * CK + c * KK + t];
    }
}

// ---------------------------------------------------------------------------
// Kernel B: offset conv (3x3, 64->27) with 2-pixel register blocking + f32x2.
// 256 threads, 2 adjacent pixels per thread (512 px / CTA).
// acc packed over output-channel pairs; weights broadcast via LDS.128.
// ---------------------------------------------------------------------------
__global__ void k_offset(const float* __restrict__ x,
                         const float* __restrict__ w_off,
                         const float* __restrict__ b_off) {
    extern __shared__ float wsr[];            // [576][28]
    int tid = threadIdx.x;                    // 256
    for (int i = tid; i < CK; i += 256) wsr[i * 28 + 27] = 0.f;
    for (int i = tid; i < 27 * CK; i += 256) {
        int o  = i / CK;
        int ct = i - o * CK;                  // c*9 + t
        wsr[ct * 28 + o] = w_off[i];
    }
    __syncthreads();

    int b  = blockIdx.y;
    int p  = blockIdx.x * 512 + tid * 2;      // even pixel, pair (p, p+1) same row
    int ho = p >> 7, wo = p & 127;

    u64 acc0[14], acc1[14];
    #pragma unroll
    for (int q = 0; q < 13; q++) { acc0[q] = pk2(b_off[2*q], b_off[2*q+1]); acc1[q] = acc0[q]; }
    acc0[13] = pk2(b_off[26], 0.f); acc1[13] = acc0[13];

    const float* xb = x + (size_t)b * CC * HW;
    #pragma unroll
    for (int t = 0; t < 9; t++) {
        int y   = ho + (t / 3) - 1;
        int xx0 = wo + (t % 3) - 1;           // px1 samples xx0+1
        if (y < 0 || y >= HH) continue;
        bool v0 = (xx0 >= 0) & (xx0 < WW);
        bool v1 = (xx0 + 1 >= 0) & (xx0 + 1 < WW);
        const float* xrow = xb + y * WW;
        #pragma unroll 2
        for (int c = 0; c < CC; c++) {
            float x0 = v0 ? xrow[(size_t)c * HW + xx0]     : 0.f;
            float x1 = v1 ? xrow[(size_t)c * HW + xx0 + 1] : 0.f;
            u64 A0 = pk2(x0, x0);
            u64 A1 = pk2(x1, x1);
            const ulonglong2* wrp = (const ulonglong2*)&wsr[(c * 9 + t) * 28];
            #pragma unroll
            for (int q = 0; q < 7; q++) {
                ulonglong2 w2 = wrp[q];
                fma2(acc0[2*q],   A0, w2.x);
                fma2(acc0[2*q+1], A0, w2.y);
                fma2(acc1[2*q],   A1, w2.x);
                fma2(acc1[2*q+1], A1, w2.y);
            }
        }
    }

    float o0[28], o1[28];
    #pragma unroll
    for (int q = 0; q < 14; q++) {
        up2(acc0[q], o0[2*q], o0[2*q+1]);
        up2(acc1[q], o1[2*q], o1[2*q+1]);
    }

    float* op = g_off + ((size_t)(b * HW + p)) * 27;
    #pragma unroll
    for (int t = 0; t < 9; t++) {
        int dty = t / 3 - 1, dtx = t % 3 - 1;
        op[t*3 + 0] = o0[t]     + (float)(ho + dty);
        op[t*3 + 1] = o0[9 + t] + (float)(wo + dtx);
        op[t*3 + 2] = 1.f / (1.f + expf(-o0[18 + t]));
        op[27 + t*3 + 0] = o1[t]     + (float)(ho + dty);
        op[27 + t*3 + 1] = o1[9 + t] + (float)(wo + 1 + dtx);
        op[27 + t*3 + 2] = 1.f / (1.f + expf(-o1[18 + t]));
    }
}

// ---------------------------------------------------------------------------
// Kernel C: per-tap fused gather + GEMM.
// CTA = 128 pixels x 64 co, 256 threads, thread tile 4 px x 8 co (f32x2 acc).
// Per tap: stage weights (bank-skewed) + gather col chunk [128px][64c], sync,
// accumulate 64 k-steps, sync. 0.31 smem B/FMA in the GEMM.
// ---------------------------------------------------------------------------
#define TP 128
#define CSTR 65     // col row stride (odd -> conflict-free scalar access)

__global__ void k_dcn(const float* __restrict__ b_dcn, float* __restrict__ out) {
    extern __shared__ float sm[];
    float* col = sm;                 // TP * CSTR = 8320 floats
    float* ws  = sm + TP * CSTR;     // 64 * 68  = 4352 floats (skewed)

    int tid = threadIdx.x;           // 256
    int b   = blockIdx.y;
    int p0  = blockIdx.x * TP;

    // Phase A mapping: 32 groups of 8 lanes
    int g     = tid >> 3;
    int lane  = tid & 7;
    int cbase = lane * 8;
    const float* xb = g_xt + (size_t)b * HW * CC;

    // GEMM mapping: 4 px x 8 co per thread
    int nt   = tid & 7;              // co group: co = nt*8 .. nt*8+7
    int mt   = tid >> 3;             // px group: px = mt*4 .. mt*4+3
    int woff = nt * 8 + (nt >> 2) * 4;

    u64 acc[4][4];
    #pragma unroll
    for (int i = 0; i < 4; i++)
        #pragma unroll
        for (int j = 0; j < 4; j++) acc[i][j] = 0ULL;

    for (int t = 0; t < 9; t++) {
        // stage tap-t weights with +4 skew per 32-co half (conflict-free LDS.128)
        const float* wsrc = g_wt + t * 64 * 64;
        #pragma unroll
        for (int idx = tid; idx < 4096; idx += 256) {
            int c = idx >> 6, co = idx & 63;
            ws[c * 68 + co + 4 * (co >> 5)] = wsrc[idx];
        }

        // gather col chunk for tap t: 128 px x 64 c
        #pragma unroll
        for (int pass = 0; pass < 4; pass++) {
            int pi = pass * 32 + g;
            int p  = p0 + pi;
            const float* op = g_off + ((size_t)(b * HW + p)) * 27 + t * 3;
            float py = op[0], pxs = op[1], mm = op[2];
            float y0f = floorf(py), x0f = floorf(pxs);
            float dy = py - y0f, dx = pxs - x0f;
            int y0 = (int)y0f, x0 = (int)x0f;
            int y1 = y0 + 1,  x1 = x0 + 1;
            bool vy0 = (y0 >= 0) & (y0 < HH);
            bool vy1 = (y1 >= 0) & (y1 < HH);
            bool vx0 = (x0 >= 0) & (x0 < WW);
            bool vx1 = (x1 >= 0) & (x1 < WW);
            float w00 = (1.f - dy) * (1.f - dx) * mm;
            float w01 = (1.f - dy) * dx * mm;
            float w10 = dy * (1.f - dx) * mm;
            float w11 = dy * dx * mm;

            float r[8];
            #pragma unroll
            for (int j = 0; j < 8; j++) r[j] = 0.f;

            if (vy0 & vx0) {
                const float4* pp = (const float4*)(xb + ((size_t)(y0 * WW + x0)) * CC + cbase);
                float4 v = pp[0];
                r[0] += w00*v.x; r[1] += w00*v.y; r[2] += w00*v.z; r[3] += w00*v.w;
                v = pp[1];
                r[4] += w00*v.x; r[5] += w00*v.y; r[6] += w00*v.z; r[7] += w00*v.w;
            }
            if (vy0 & vx1) {
                const float4* pp = (const float4*)(xb + ((size_t)(y0 * WW + x1)) * CC + cbase);
                float4 v = pp[0];
                r[0] += w01*v.x; r[1] += w01*v.y; r[2] += w01*v.z; r[3] += w01*v.w;
                v = pp[1];
                r[4] += w01*v.x; r[5] += w01*v.y; r[6] += w01*v.z; r[7] += w01*v.w;
            }
            if (vy1 & vx0) {
                const float4* pp = (const float4*)(xb + ((size_t)(y1 * WW + x0)) * CC + cbase);
                float4 v = pp[0];
                r[0] += w10*v.x; r[1] += w10*v.y; r[2] += w10*v.z; r[3] += w10*v.w;
                v = pp[1];
                r[4] += w10*v.x; r[5] += w10*v.y; r[6] += w10*v.z; r[7] += w10*v.w;
            }
            if (vy1 & vx1) {
                const float4* pp = (const float4*)(xb + ((size_t)(y1 * WW + x1)) * CC + cbase);
                float4 v = pp[0];
                r[0] += w11*v.x; r[1] += w11*v.y; r[2] += w11*v.z; r[3] += w11*v.w;
                v = pp[1];
                r[4] += w11*v.x; r[5] += w11*v.y; r[6] += w11*v.z; r[7] += w11*v.w;
            }

            float* cd = &col[pi * CSTR + cbase];
            #pragma unroll
            for (int j = 0; j < 8; j++) cd[j] = r[j];
        }
        __syncthreads();

        // GEMM accumulate over this tap's 64 k-steps
        const float* arow = col + mt * 4 * CSTR;
        #pragma unroll 4
        for (int c = 0; c < 64; c++) {
            float a0 = arow[c];
            float a1 = arow[CSTR + c];
            float a2 = arow[2 * CSTR + c];
            float a3 = arow[3 * CSTR + c];
            u64 A0 = pk2(a0, a0), A1 = pk2(a1, a1);
            u64 A2 = pk2(a2, a2), A3 = pk2(a3, a3);
            ulonglong2 b01 = *(const ulonglong2*)&ws[c * 68 + woff];
            ulonglong2 b23 = *(const ulonglong2*)&ws[c * 68 + woff + 4];
            fma2(acc[0][0], A0, b01.x); fma2(acc[0][1], A0, b01.y);
            fma2(acc[0][2], A0, b23.x); fma2(acc[0][3], A0, b23.y);
            fma2(acc[1][0], A1, b01.x); fma2(acc[1][1], A1, b01.y);
            fma2(acc[1][2], A1, b23.x); fma2(acc[1][3], A1, b23.y);
            fma2(acc[2][0], A2, b01.x); fma2(acc[2][1], A2, b01.y);
            fma2(acc[2][2], A2, b23.x); fma2(acc[2][3], A2, b23.y);
            fma2(acc[3][0], A3, b01.x); fma2(acc[3][1], A3, b01.y);
            fma2(acc[3][2], A3, b23.x); fma2(acc[3][3], A3, b23.y);
        }
        __syncthreads();
    }

    // epilogue: thread owns px = p0+mt*4..+3, co = nt*8..+7; float4 over px
    float* ob = out + (size_t)b * CO * HW + p0 + mt * 4;
    #pragma unroll
    for (int j = 0; j < 4; j++) {
        int co = nt * 8 + 2 * j;
        float bl = b_dcn[co], bh = b_dcn[co + 1];
        float l0, h0, l1, h1, l2, h2, l3, h3;
        up2(acc[0][j], l0, h0); up2(acc[1][j], l1, h1);
        up2(acc[2][j], l2, h2); up2(acc[3][j], l3, h3);
        float4 vlo = make_float4(l0 + bl, l1 + bl, l2 + bl, l3 + bl);
        float4 vhi = make_float4(h0 + bh, h1 + bh, h2 + bh, h3 + bh);
        *(float4*)(ob + (size_t)co * HW)       = vlo;
        *(float4*)(ob + (size_t)(co + 1) * HW) = vhi;
    }
}

// ---------------------------------------------------------------------------
extern "C" void kernel_launch(void* const* d_in, const int* in_sizes, int n_in,
                              void* d_out, int out_size) {
    const float* x        = (const float*)d_in[0];
    const float* w_offset = (const float*)d_in[1];
    const float* b_offset = (const float*)d_in[2];
    const float* w_dcn    = (const float*)d_in[3];
    const float* b_dcn    = (const float*)d_in[4];
    float* out = (float*)d_out;

    const int SMEM_B = CK * 28 * 4;                        // 64512
    const int SMEM_C = (TP * CSTR + 64 * 68) * 4;          // 50688
    cudaFuncSetAttribute(k_offset, cudaFuncAttributeMaxDynamicSharedMemorySize, SMEM_B);
    cudaFuncSetAttribute(k_dcn,    cudaFuncAttributeMaxDynamicSharedMemorySize, SMEM_C);

    k_transpose<<<dim3(HW / 32, CC / 32, BB), dim3(32, 8)>>>(x);
    k_wreorder<<<(CK * CO + 255) / 256, 256>>>(w_dcn);
    k_offset<<<dim3(HW / 512, BB), 256, SMEM_B>>>(x, w_offset, b_offset);
    k_dcn<<<dim3(HW / TP, BB), 256, SMEM_C>>>(b_dcn, out);
}

// round 3
// speedup vs baseline: 3.2527x; 1.0873x over previous
#include <cuda_runtime.h>
#include <math.h>

#define BB 8
#define CC 64
#define HH 128
#define WW 128
#define HW (HH*WW)
#define KK 9
#define CO 64
#define CK (CC*KK)   // 576

typedef unsigned long long u64;

__device__ float g_xt[BB*HW*CC];      // x transposed to NHWC
__device__ float g_off[BB*HW*KK*3];   // per (pixel,tap): py,px,mask
__device__ float g_wt[CK*CO];         // reordered dcn weight [(t*64+c)][co]

__device__ __forceinline__ u64 pk2(float lo, float hi) {
    u64 r; asm("mov.b64 %0,{%1,%2};" : "=l"(r) : "f"(lo), "f"(hi)); return r;
}
__device__ __forceinline__ u64 pk2s(float a) {
    u64 r; asm("mov.b64 %0,{%1,%1};" : "=l"(r) : "f"(a)); return r;
}
__device__ __forceinline__ void fma2(u64 &d, u64 a, u64 b) {
    asm("fma.rn.f32x2 %0,%1,%2,%0;" : "+l"(d) : "l"(a), "l"(b));
}
__device__ __forceinline__ void up2(u64 v, float &a, float &b) {
    asm("mov.b64 {%0,%1},%2;" : "=f"(a), "=f"(b) : "l"(v));
}

// ---------------------------------------------------------------------------
// Kernel A: NCHW -> NHWC transpose
// ---------------------------------------------------------------------------
__global__ void k_transpose(const float* __restrict__ x) {
    __shared__ float tile[32][33];
    int b  = blockIdx.z;
    int p0 = blockIdx.x * 32;
    int c0 = blockIdx.y * 32;
    int tx = threadIdx.x, ty = threadIdx.y;   // 32 x 8
    const float* xb = x + (size_t)b * CC * HW;
    #pragma unroll
    for (int i = 0; i < 32; i += 8)
        tile[ty + i][tx] = xb[(size_t)(c0 + ty + i) * HW + p0 + tx];
    __syncthreads();
    float* xo = g_xt + (size_t)b * HW * CC;
    #pragma unroll
    for (int i = 0; i < 32; i += 8)
        xo[(size_t)(p0 + ty + i) * CC + c0 + tx] = tile[tx][ty + i];
}

// ---------------------------------------------------------------------------
// Kernel W: reorder w_dcn [co][c][t] -> g_wt[(t*64+c)][co]
// ---------------------------------------------------------------------------
__global__ void k_wreorder(const float* __restrict__ wd) {
    int idx = blockIdx.x * 256 + threadIdx.x;
    if (idx < CK * CO) {
        int j = idx >> 6, co = idx & 63;
        int t = j >> 6, c = j & 63;
        g_wt[idx] = wd[co * CK + c * KK + t];
    }
}

// ---------------------------------------------------------------------------
// Kernel B: offset conv (3x3, 64->27), 2 px per thread, f32x2 accumulators.
// ---------------------------------------------------------------------------
__global__ void k_offset(const float* __restrict__ x,
                         const float* __restrict__ w_off,
                         const float* __restrict__ b_off) {
    extern __shared__ float wsr[];            // [576][28]
    int tid = threadIdx.x;                    // 256
    for (int i = tid; i < CK; i += 256) wsr[i * 28 + 27] = 0.f;
    for (int i = tid; i < 27 * CK; i += 256) {
        int o  = i / CK;
        int ct = i - o * CK;                  // c*9 + t
        wsr[ct * 28 + o] = w_off[i];
    }
    __syncthreads();

    int b  = blockIdx.y;
    int p  = blockIdx.x * 512 + tid * 2;
    int ho = p >> 7, wo = p & 127;

    u64 acc0[14], acc1[14];
    #pragma unroll
    for (int q = 0; q < 13; q++) { acc0[q] = pk2(b_off[2*q], b_off[2*q+1]); acc1[q] = acc0[q]; }
    acc0[13] = pk2(b_off[26], 0.f); acc1[13] = acc0[13];

    const float* xb = x + (size_t)b * CC * HW;
    #pragma unroll
    for (int t = 0; t < 9; t++) {
        int y   = ho + (t / 3) - 1;
        int xx0 = wo + (t % 3) - 1;
        if (y < 0 || y >= HH) continue;
        bool v0 = (xx0 >= 0) & (xx0 < WW);
        bool v1 = (xx0 + 1 >= 0) & (xx0 + 1 < WW);
        const float* xrow = xb + y * WW;
        #pragma unroll 2
        for (int c = 0; c < CC; c++) {
            float x0 = v0 ? xrow[(size_t)c * HW + xx0]     : 0.f;
            float x1 = v1 ? xrow[(size_t)c * HW + xx0 + 1] : 0.f;
            u64 A0 = pk2s(x0);
            u64 A1 = pk2s(x1);
            const ulonglong2* wrp = (const ulonglong2*)&wsr[(c * 9 + t) * 28];
            #pragma unroll
            for (int q = 0; q < 7; q++) {
                ulonglong2 w2 = wrp[q];
                fma2(acc0[2*q],   A0, w2.x);
                fma2(acc0[2*q+1], A0, w2.y);
                fma2(acc1[2*q],   A1, w2.x);
                fma2(acc1[2*q+1], A1, w2.y);
            }
        }
    }

    float o0[28], o1[28];
    #pragma unroll
    for (int q = 0; q < 14; q++) {
        up2(acc0[q], o0[2*q], o0[2*q+1]);
        up2(acc1[q], o1[2*q], o1[2*q+1]);
    }

    float* op = g_off + ((size_t)(b * HW + p)) * 27;
    #pragma unroll
    for (int t = 0; t < 9; t++) {
        int dty = t / 3 - 1, dtx = t % 3 - 1;
        op[t*3 + 0] = o0[t]     + (float)(ho + dty);
        op[t*3 + 1] = o0[9 + t] + (float)(wo + dtx);
        op[t*3 + 2] = 1.f / (1.f + __expf(-o0[18 + t]));
        op[27 + t*3 + 0] = o1[t]     + (float)(ho + dty);
        op[27 + t*3 + 1] = o1[9 + t] + (float)(wo + 1 + dtx);
        op[27 + t*3 + 2] = 1.f / (1.f + __expf(-o1[18 + t]));
    }
}

// ---------------------------------------------------------------------------
// Kernel C: per-tap fused gather + GEMM.
// CTA = 128 px x 64 co, 256 threads, thread tile 4 px x 8 co, f32x2 acc.
// GEMM processes k in chunks of 4 with vectorized col loads:
//   per chunk: 4 LDS.128 (col) + 8 LDS.128 (weights) -> 64 FFMA2.
// ---------------------------------------------------------------------------
#define TP 128
#define CSTR 68     // 16B-aligned col row stride

__global__ void k_dcn(const float* __restrict__ b_dcn, float* __restrict__ out) {
    extern __shared__ float sm[];
    float* col = sm;                 // TP * CSTR = 8704 floats
    float* ws  = sm + TP * CSTR;     // 64 * 68  = 4352 floats (skewed)

    int tid = threadIdx.x;           // 256
    int b   = blockIdx.y;
    int p0  = blockIdx.x * TP;

    // Phase A mapping: 32 groups of 8 lanes
    int g     = tid >> 3;
    int lane  = tid & 7;
    int cbase = lane * 8;
    const float* xb = g_xt + (size_t)b * HW * CC;

    // GEMM mapping: 4 consecutive px x 8 co per thread
    int nt   = tid & 7;
    int mt   = tid >> 3;
    int woff = nt * 8 + (nt >> 2) * 4;

    u64 acc[4][4];
    #pragma unroll
    for (int i = 0; i < 4; i++)
        #pragma unroll
        for (int j = 0; j < 4; j++) acc[i][j] = 0ULL;

    #pragma unroll 1
    for (int t = 0; t < 9; t++) {
        // stage tap-t weights with +4 skew per 32-co half
        const float* wsrc = g_wt + t * 64 * 64;
        #pragma unroll
        for (int idx = tid; idx < 4096; idx += 256) {
            int c = idx >> 6, co = idx & 63;
            ws[c * 68 + co + 4 * (co >> 5)] = wsrc[idx];
        }

        // gather col chunk for tap t: 128 px x 64 c
        #pragma unroll
        for (int pass = 0; pass < 4; pass++) {
            int pi = pass * 32 + g;
            int p  = p0 + pi;
            const float* op = g_off + ((size_t)(b * HW + p)) * 27 + t * 3;
            float py = op[0], pxs = op[1], mm = op[2];
            float y0f = floorf(py), x0f = floorf(pxs);
            float dy = py - y0f, dx = pxs - x0f;
            int y0 = (int)y0f, x0 = (int)x0f;
            int y1 = y0 + 1,  x1 = x0 + 1;
            bool vy0 = (y0 >= 0) & (y0 < HH);
            bool vy1 = (y1 >= 0) & (y1 < HH);
            bool vx0 = (x0 >= 0) & (x0 < WW);
            bool vx1 = (x1 >= 0) & (x1 < WW);
            float w00 = (1.f - dy) * (1.f - dx) * mm;
            float w01 = (1.f - dy) * dx * mm;
            float w10 = dy * (1.f - dx) * mm;
            float w11 = dy * dx * mm;

            float r[8];
            #pragma unroll
            for (int j = 0; j < 8; j++) r[j] = 0.f;

            if (vy0 & vx0) {
                const float4* pp = (const float4*)(xb + ((size_t)(y0 * WW + x0)) * CC + cbase);
                float4 v = pp[0];
                r[0] += w00*v.x; r[1] += w00*v.y; r[2] += w00*v.z; r[3] += w00*v.w;
                v = pp[1];
                r[4] += w00*v.x; r[5] += w00*v.y; r[6] += w00*v.z; r[7] += w00*v.w;
            }
            if (vy0 & vx1) {
                const float4* pp = (const float4*)(xb + ((size_t)(y0 * WW + x1)) * CC + cbase);
                float4 v = pp[0];
                r[0] += w01*v.x; r[1] += w01*v.y; r[2] += w01*v.z; r[3] += w01*v.w;
                v = pp[1];
                r[4] += w01*v.x; r[5] += w01*v.y; r[6] += w01*v.z; r[7] += w01*v.w;
            }
            if (vy1 & vx0) {
                const float4* pp = (const float4*)(xb + ((size_t)(y1 * WW + x0)) * CC + cbase);
                float4 v = pp[0];
                r[0] += w10*v.x; r[1] += w10*v.y; r[2] += w10*v.z; r[3] += w10*v.w;
                v = pp[1];
                r[4] += w10*v.x; r[5] += w10*v.y; r[6] += w10*v.z; r[7] += w10*v.w;
            }
            if (vy1 & vx1) {
                const float4* pp = (const float4*)(xb + ((size_t)(y1 * WW + x1)) * CC + cbase);
                float4 v = pp[0];
                r[0] += w11*v.x; r[1] += w11*v.y; r[2] += w11*v.z; r[3] += w11*v.w;
                v = pp[1];
                r[4] += w11*v.x; r[5] += w11*v.y; r[6] += w11*v.z; r[7] += w11*v.w;
            }

            float* cd = &col[pi * CSTR + cbase];
            #pragma unroll
            for (int j = 0; j < 8; j++) cd[j] = r[j];
        }
        __syncthreads();

        // GEMM accumulate: chunks of 4 k-steps, vectorized col loads
        const float* arow = col + mt * 4 * CSTR;
        #pragma unroll
        for (int cb = 0; cb < 64; cb += 4) {
            float4 A0 = *(const float4*)(arow + cb);
            float4 A1 = *(const float4*)(arow + CSTR + cb);
            float4 A2 = *(const float4*)(arow + 2 * CSTR + cb);
            float4 A3 = *(const float4*)(arow + 3 * CSTR + cb);
            const float* a0p = (const float*)&A0;
            const float* a1p = (const float*)&A1;
            const float* a2p = (const float*)&A2;
            const float* a3p = (const float*)&A3;
            #pragma unroll
            for (int cc = 0; cc < 4; cc++) {
                ulonglong2 b01 = *(const ulonglong2*)&ws[(cb + cc) * 68 + woff];
                ulonglong2 b23 = *(const ulonglong2*)&ws[(cb + cc) * 68 + woff + 4];
                u64 P0 = pk2s(a0p[cc]);
                u64 P1 = pk2s(a1p[cc]);
                u64 P2 = pk2s(a2p[cc]);
                u64 P3 = pk2s(a3p[cc]);
                fma2(acc[0][0], P0, b01.x); fma2(acc[0][1], P0, b01.y);
                fma2(acc[0][2], P0, b23.x); fma2(acc[0][3], P0, b23.y);
                fma2(acc[1][0], P1, b01.x); fma2(acc[1][1], P1, b01.y);
                fma2(acc[1][2], P1, b23.x); fma2(acc[1][3], P1, b23.y);
                fma2(acc[2][0], P2, b01.x); fma2(acc[2][1], P2, b01.y);
                fma2(acc[2][2], P2, b23.x); fma2(acc[2][3], P2, b23.y);
                fma2(acc[3][0], P3, b01.x); fma2(acc[3][1], P3, b01.y);
                fma2(acc[3][2], P3, b23.x); fma2(acc[3][3], P3, b23.y);
            }
        }
        __syncthreads();
    }

    // epilogue: px = p0+mt*4..+3, co = nt*8..+7; float4 over px
    float* ob = out + (size_t)b * CO * HW + p0 + mt * 4;
    #pragma unroll
    for (int j = 0; j < 4; j++) {
        int co = nt * 8 + 2 * j;
        float bl = b_dcn[co], bh = b_dcn[co + 1];
        float l0, h0, l1, h1, l2, h2, l3, h3;
        up2(acc[0][j], l0, h0); up2(acc[1][j], l1, h1);
        up2(acc[2][j], l2, h2); up2(acc[3][j], l3, h3);
        float4 vlo = make_float4(l0 + bl, l1 + bl, l2 + bl, l3 + bl);
        float4 vhi = make_float4(h0 + bh, h1 + bh, h2 + bh, h3 + bh);
        *(float4*)(ob + (size_t)co * HW)       = vlo;
        *(float4*)(ob + (size_t)(co + 1) * HW) = vhi;
    }
}

// ---------------------------------------------------------------------------
extern "C" void kernel_launch(void* const* d_in, const int* in_sizes, int n_in,
                              void* d_out, int out_size) {
    const float* x        = (const float*)d_in[0];
    const float* w_offset = (const float*)d_in[1];
    const float* b_offset = (const float*)d_in[2];
    const float* w_dcn    = (const float*)d_in[3];
    const float* b_dcn    = (const float*)d_in[4];
    float* out = (float*)d_out;

    const int SMEM_B = CK * 28 * 4;                        // 64512
    const int SMEM_C = (TP * CSTR + 64 * 68) * 4;          // 52224
    cudaFuncSetAttribute(k_offset, cudaFuncAttributeMaxDynamicSharedMemorySize, SMEM_B);
    cudaFuncSetAttribute(k_dcn,    cudaFuncAttributeMaxDynamicSharedMemorySize, SMEM_C);

    k_transpose<<<dim3(HW / 32, CC / 32, BB), dim3(32, 8)>>>(x);
    k_wreorder<<<(CK * CO + 255) / 256, 256>>>(w_dcn);
    k_offset<<<dim3(HW / 512, BB), 256, SMEM_B>>>(x, w_offset, b_offset);
    k_dcn<<<dim3(HW / TP, BB), 256, SMEM_C>>>(b_dcn, out);
}

// round 4
// speedup vs baseline: 4.4948x; 1.3818x over previous
#include <cuda_runtime.h>
#include <cuda_fp16.h>
#include <math.h>

#define BB 8
#define CC 64
#define HH 128
#define WW 128
#define HW (HH*WW)
#define KK 9
#define CO 64
#define CK (CC*KK)   // 576

typedef unsigned long long u64;
typedef unsigned int u32;

__device__ float  g_xt[BB*HW*CC];       // x transposed to NHWC (fp32)
__device__ float  g_off[BB*HW*KK*3];    // per (pixel,tap): py,px,mask
__device__ __half g_wth[KK*CO*CC];      // fp16 weights [t][co][k=c]

__device__ __forceinline__ u64 pk2(float lo, float hi) {
    u64 r; asm("mov.b64 %0,{%1,%2};" : "=l"(r) : "f"(lo), "f"(hi)); return r;
}
__device__ __forceinline__ u64 pk2s(float a) {
    u64 r; asm("mov.b64 %0,{%1,%1};" : "=l"(r) : "f"(a)); return r;
}
__device__ __forceinline__ void fma2(u64 &d, u64 a, u64 b) {
    asm("fma.rn.f32x2 %0,%1,%2,%0;" : "+l"(d) : "l"(a), "l"(b));
}
__device__ __forceinline__ void up2(u64 v, float &a, float &b) {
    asm("mov.b64 {%0,%1},%2;" : "=f"(a), "=f"(b) : "l"(v));
}

// ---------------------------------------------------------------------------
// Kernel A: NCHW -> NHWC transpose
// ---------------------------------------------------------------------------
__global__ void k_transpose(const float* __restrict__ x) {
    __shared__ float tile[32][33];
    int b  = blockIdx.z;
    int p0 = blockIdx.x * 32;
    int c0 = blockIdx.y * 32;
    int tx = threadIdx.x, ty = threadIdx.y;   // 32 x 8
    const float* xb = x + (size_t)b * CC * HW;
    #pragma unroll
    for (int i = 0; i < 32; i += 8)
        tile[ty + i][tx] = xb[(size_t)(c0 + ty + i) * HW + p0 + tx];
    __syncthreads();
    float* xo = g_xt + (size_t)b * HW * CC;
    #pragma unroll
    for (int i = 0; i < 32; i += 8)
        xo[(size_t)(p0 + ty + i) * CC + c0 + tx] = tile[tx][ty + i];
}

// ---------------------------------------------------------------------------
// Kernel W: w_dcn [co][c][t] -> g_wth[t][co][c] (fp16)
// ---------------------------------------------------------------------------
__global__ void k_wreorder(const float* __restrict__ wd) {
    int idx = blockIdx.x * 256 + threadIdx.x;   // t*4096 + co*64 + c
    if (idx < KK * CO * CC) {
        int t  = idx >> 12;
        int co = (idx >> 6) & 63;
        int c  = idx & 63;
        g_wth[idx] = __float2half(wd[co * CK + c * KK + t]);
    }
}

// ---------------------------------------------------------------------------
// Kernel B: offset conv (3x3, 64->27), 2 px per thread, f32x2 accumulators.
// ---------------------------------------------------------------------------
__global__ void k_offset(const float* __restrict__ x,
                         const float* __restrict__ w_off,
                         const float* __restrict__ b_off) {
    extern __shared__ float wsr[];            // [576][28]
    int tid = threadIdx.x;                    // 256
    for (int i = tid; i < CK; i += 256) wsr[i * 28 + 27] = 0.f;
    for (int i = tid; i < 27 * CK; i += 256) {
        int o  = i / CK;
        int ct = i - o * CK;                  // c*9 + t
        wsr[ct * 28 + o] = w_off[i];
    }
    __syncthreads();

    int b  = blockIdx.y;
    int p  = blockIdx.x * 512 + tid * 2;
    int ho = p >> 7, wo = p & 127;

    u64 acc0[14], acc1[14];
    #pragma unroll
    for (int q = 0; q < 13; q++) { acc0[q] = pk2(b_off[2*q], b_off[2*q+1]); acc1[q] = acc0[q]; }
    acc0[13] = pk2(b_off[26], 0.f); acc1[13] = acc0[13];

    const float* xb = x + (size_t)b * CC * HW;
    #pragma unroll
    for (int t = 0; t < 9; t++) {
        int y   = ho + (t / 3) - 1;
        int xx0 = wo + (t % 3) - 1;
        if (y < 0 || y >= HH) continue;
        bool v0 = (xx0 >= 0) & (xx0 < WW);
        bool v1 = (xx0 + 1 >= 0) & (xx0 + 1 < WW);
        const float* xrow = xb + y * WW;
        #pragma unroll 2
        for (int c = 0; c < CC; c++) {
            float x0 = v0 ? xrow[(size_t)c * HW + xx0]     : 0.f;
            float x1 = v1 ? xrow[(size_t)c * HW + xx0 + 1] : 0.f;
            u64 A0 = pk2s(x0);
            u64 A1 = pk2s(x1);
            const ulonglong2* wrp = (const ulonglong2*)&wsr[(c * 9 + t) * 28];
            #pragma unroll
            for (int q = 0; q < 7; q++) {
                ulonglong2 w2 = wrp[q];
                fma2(acc0[2*q],   A0, w2.x);
                fma2(acc0[2*q+1], A0, w2.y);
                fma2(acc1[2*q],   A1, w2.x);
                fma2(acc1[2*q+1], A1, w2.y);
            }
        }
    }

    float o0[28], o1[28];
    #pragma unroll
    for (int q = 0; q < 14; q++) {
        up2(acc0[q], o0[2*q], o0[2*q+1]);
        up2(acc1[q], o1[2*q], o1[2*q+1]);
    }

    float* op = g_off + ((size_t)(b * HW + p)) * 27;
    #pragma unroll
    for (int t = 0; t < 9; t++) {
        int dty = t / 3 - 1, dtx = t % 3 - 1;
        op[t*3 + 0] = o0[t]     + (float)(ho + dty);
        op[t*3 + 1] = o0[9 + t] + (float)(wo + dtx);
        op[t*3 + 2] = 1.f / (1.f + __expf(-o0[18 + t]));
        op[27 + t*3 + 0] = o1[t]     + (float)(ho + dty);
        op[27 + t*3 + 1] = o1[9 + t] + (float)(wo + 1 + dtx);
        op[27 + t*3 + 2] = 1.f / (1.f + __expf(-o1[18 + t]));
    }
}

// ---------------------------------------------------------------------------
// Kernel C: per-tap fused gather (fp32 math -> fp16 col) + tensor-core GEMM.
// CTA = 128 px x 64 co, 256 threads = 8 warps.
// Warp tile: 16 co x 64 px, mma.sync m16n8k16 f16 with fp32 accumulate.
// col row stride CSTRH=72 halves -> fragment LDS hit banks 4*gid+tig (all 32).
// ---------------------------------------------------------------------------
#define TP 128
#define CSTRH 72

__global__ void k_dcn(const float* __restrict__ b_dcn, float* __restrict__ out) {
    extern __shared__ __half smh[];
    __half* col = smh;                    // TP * CSTRH = 9216 halves (18 KB)
    __half* wsT = smh + TP * CSTRH;       // 64 * CSTRH = 4608 halves (9 KB)

    int tid = threadIdx.x;                // 256
    int b   = blockIdx.y;
    int p0  = blockIdx.x * TP;

    // Phase A mapping: 32 groups of 8 lanes
    int g     = tid >> 3;
    int lane8 = tid & 7;
    int cbase = lane8 * 8;
    const float* xb = g_xt + (size_t)b * HW * CC;

    // GEMM mapping
    int lane   = tid & 31;
    int w      = tid >> 5;                // 8 warps
    int cobase = (w & 3) * 16;
    int pxh    = (w >> 2) * 64;
    int gid    = lane >> 2;
    int tig    = lane & 3;

    float acc[8][4];
    #pragma unroll
    for (int i = 0; i < 8; i++)
        #pragma unroll
        for (int j = 0; j < 4; j++) acc[i][j] = 0.f;

    #pragma unroll 1
    for (int t = 0; t < 9; t++) {
        // stage tap-t fp16 weights [co][k], stride CSTRH
        const u32* wsrc = (const u32*)(g_wth + t * CO * CC);
        #pragma unroll
        for (int idx = tid; idx < 2048; idx += 256) {
            int co = idx >> 5, kp = idx & 31;
            *(u32*)&wsT[co * CSTRH + kp * 2] = wsrc[co * 32 + kp];
        }

        // gather col chunk for tap t: 128 px x 64 c (fp32 math, fp16 store)
        #pragma unroll
        for (int pass = 0; pass < 4; pass++) {
            int pi = pass * 32 + g;
            int p  = p0 + pi;
            const float* op = g_off + ((size_t)(b * HW + p)) * 27 + t * 3;
            float py = op[0], pxs = op[1], mm = op[2];
            float y0f = floorf(py), x0f = floorf(pxs);
            float dy = py - y0f, dx = pxs - x0f;
            int y0 = (int)y0f, x0 = (int)x0f;
            int y1 = y0 + 1,  x1 = x0 + 1;
            bool vy0 = (y0 >= 0) & (y0 < HH);
            bool vy1 = (y1 >= 0) & (y1 < HH);
            bool vx0 = (x0 >= 0) & (x0 < WW);
            bool vx1 = (x1 >= 0) & (x1 < WW);
            float w00 = (1.f - dy) * (1.f - dx) * mm;
            float w01 = (1.f - dy) * dx * mm;
            float w10 = dy * (1.f - dx) * mm;
            float w11 = dy * dx * mm;

            float r[8];
            #pragma unroll
            for (int j = 0; j < 8; j++) r[j] = 0.f;

            if (vy0 & vx0) {
                const float4* pp = (const float4*)(xb + ((size_t)(y0 * WW + x0)) * CC + cbase);
                float4 v = pp[0];
                r[0] += w00*v.x; r[1] += w00*v.y; r[2] += w00*v.z; r[3] += w00*v.w;
                v = pp[1];
                r[4] += w00*v.x; r[5] += w00*v.y; r[6] += w00*v.z; r[7] += w00*v.w;
            }
            if (vy0 & vx1) {
                const float4* pp = (const float4*)(xb + ((size_t)(y0 * WW + x1)) * CC + cbase);
                float4 v = pp[0];
                r[0] += w01*v.x; r[1] += w01*v.y; r[2] += w01*v.z; r[3] += w01*v.w;
                v = pp[1];
                r[4] += w01*v.x; r[5] += w01*v.y; r[6] += w01*v.z; r[7] += w01*v.w;
            }
            if (vy1 & vx0) {
                const float4* pp = (const float4*)(xb + ((size_t)(y1 * WW + x0)) * CC + cbase);
                float4 v = pp[0];
                r[0] += w10*v.x; r[1] += w10*v.y; r[2] += w10*v.z; r[3] += w10*v.w;
                v = pp[1];
                r[4] += w10*v.x; r[5] += w10*v.y; r[6] += w10*v.z; r[7] += w10*v.w;
            }
            if (vy1 & vx1) {
                const float4* pp = (const float4*)(xb + ((size_t)(y1 * WW + x1)) * CC + cbase);
                float4 v = pp[0];
                r[0] += w11*v.x; r[1] += w11*v.y; r[2] += w11*v.z; r[3] += w11*v.w;
                v = pp[1];
                r[4] += w11*v.x; r[5] += w11*v.y; r[6] += w11*v.z; r[7] += w11*v.w;
            }

            __half2 h0 = __floats2half2_rn(r[0], r[1]);
            __half2 h1 = __floats2half2_rn(r[2], r[3]);
            __half2 h2 = __floats2half2_rn(r[4], r[5]);
            __half2 h3 = __floats2half2_rn(r[6], r[7]);
            uint4 pack = make_uint4(*(u32*)&h0, *(u32*)&h1, *(u32*)&h2, *(u32*)&h3);
            *(uint4*)&col[pi * CSTRH + cbase] = pack;
        }
        __syncthreads();

        // tensor-core GEMM over this tap's k=64 (4 k-steps of 16)
        #pragma unroll
        for (int ks = 0; ks < 4; ks++) {
            int kb = ks * 16 + 2 * tig;
            u32 a0 = *(u32*)&wsT[(cobase + gid)     * CSTRH + kb];
            u32 a1 = *(u32*)&wsT[(cobase + gid + 8) * CSTRH + kb];
            u32 a2 = *(u32*)&wsT[(cobase + gid)     * CSTRH + kb + 8];
            u32 a3 = *(u32*)&wsT[(cobase + gid + 8) * CSTRH + kb + 8];
            #pragma unroll
            for (int nt = 0; nt < 8; nt++) {
                const __half* brow = &col[(pxh + nt * 8 + gid) * CSTRH + kb];
                u32 b0 = *(const u32*)brow;
                u32 b1 = *(const u32*)(brow + 8);
                asm volatile(
                    "mma.sync.aligned.m16n8k16.row.col.f32.f16.f16.f32 "
                    "{%0,%1,%2,%3}, {%4,%5,%6,%7}, {%8,%9}, {%0,%1,%2,%3};"
                    : "+f"(acc[nt][0]), "+f"(acc[nt][1]),
                      "+f"(acc[nt][2]), "+f"(acc[nt][3])
                    : "r"(a0), "r"(a1), "r"(a2), "r"(a3), "r"(b0), "r"(b1));
            }
        }
        __syncthreads();
    }

    // epilogue: D[m=co][n=px]; c0,c1 = row gid, cols 2tig,2tig+1; c2,c3 = row gid+8
    float bl = b_dcn[cobase + gid];
    float bh = b_dcn[cobase + gid + 8];
    float* ob = out + (size_t)b * CO * HW + p0 + pxh + 2 * tig;
    #pragma unroll
    for (int nt = 0; nt < 8; nt++) {
        float2 vlo = make_float2(acc[nt][0] + bl, acc[nt][1] + bl);
        float2 vhi = make_float2(acc[nt][2] + bh, acc[nt][3] + bh);
        *(float2*)(ob + (size_t)(cobase + gid)     * HW + nt * 8) = vlo;
        *(float2*)(ob + (size_t)(cobase + gid + 8) * HW + nt * 8) = vhi;
    }
}

// ---------------------------------------------------------------------------
extern "C" void kernel_launch(void* const* d_in, const int* in_sizes, int n_in,
                              void* d_out, int out_size) {
    const float* x        = (const float*)d_in[0];
    const float* w_offset = (const float*)d_in[1];
    const float* b_offset = (const float*)d_in[2];
    const float* w_dcn    = (const float*)d_in[3];
    const float* b_dcn    = (const float*)d_in[4];
    float* out = (float*)d_out;

    const int SMEM_B = CK * 28 * 4;                          // 64512
    const int SMEM_C = (TP * CSTRH + CO * CSTRH) * 2;        // 27648
    cudaFuncSetAttribute(k_offset, cudaFuncAttributeMaxDynamicSharedMemorySize, SMEM_B);
    cudaFuncSetAttribute(k_dcn,    cudaFuncAttributeMaxDynamicSharedMemorySize, SMEM_C);

    k_transpose<<<dim3(HW / 32, CC / 32, BB), dim3(32, 8)>>>(x);
    k_wreorder<<<(KK * CO * CC + 255) / 256, 256>>>(w_dcn);
    k_offset<<<dim3(HW / 512, BB), 256, SMEM_B>>>(x, w_offset, b_offset);
    k_dcn<<<dim3(HW / TP, BB), 256, SMEM_C>>>(b_dcn, out);
}

// round 5
// speedup vs baseline: 6.9531x; 1.5469x over previous
#include <cuda_runtime.h>
#include <cuda_fp16.h>
#include <math.h>

#define BB 8
#define CC 64
#define HH 128
#define WW 128
#define HW (HH*WW)
#define KK 9
#define CO 64
#define CK (CC*KK)   // 576

typedef unsigned long long u64;
typedef unsigned int u32;

__device__ float  g_xt [BB*HW*CC];      // x NHWC fp32 (bilinear source)
__device__ __half g_xth[BB*HW*CC];      // x NHWC fp16 (offset-conv source)
__device__ float  g_off[BB*27*HW];      // planar: [b][plane][HW]; plane t=py_t, 9+t=px_t, 18+t=m_t
__device__ __half g_wth[KK*CO*CC];      // dcn weights [t][co][c] fp16
__device__ __half g_woh[KK*32*CC];      // offset weights [t][o pad32][c] fp16

// ---------------------------------------------------------------------------
// Kernel A: NCHW -> NHWC transpose (fp32 + fp16 copies)
// ---------------------------------------------------------------------------
__global__ void k_transpose(const float* __restrict__ x) {
    __shared__ float tile[32][33];
    int b  = blockIdx.z;
    int p0 = blockIdx.x * 32;
    int c0 = blockIdx.y * 32;
    int tx = threadIdx.x, ty = threadIdx.y;   // 32 x 8
    const float* xb = x + (size_t)b * CC * HW;
    #pragma unroll
    for (int i = 0; i < 32; i += 8)
        tile[ty + i][tx] = xb[(size_t)(c0 + ty + i) * HW + p0 + tx];
    __syncthreads();
    float*  xo  = g_xt  + (size_t)b * HW * CC;
    __half* xoh = g_xth + (size_t)b * HW * CC;
    #pragma unroll
    for (int i = 0; i < 32; i += 8) {
        float v = tile[tx][ty + i];
        size_t o = (size_t)(p0 + ty + i) * CC + c0 + tx;
        xo[o]  = v;
        xoh[o] = __float2half(v);
    }
}

// ---------------------------------------------------------------------------
// Kernel W: weight reorder/convert for both GEMMs
// ---------------------------------------------------------------------------
__global__ void k_wreorder(const float* __restrict__ wd, const float* __restrict__ wo) {
    int idx = blockIdx.x * 256 + threadIdx.x;
    if (idx < KK * CO * CC) {                 // dcn: [t][co][c]
        int t  = idx >> 12;
        int co = (idx >> 6) & 63;
        int c  = idx & 63;
        g_wth[idx] = __float2half(wd[co * CK + c * KK + t]);
    }
    if (idx < KK * 32 * CC) {                 // offset: [t][o pad32][c]
        int t = idx >> 11;
        int o = (idx >> 6) & 31;
        int c = idx & 63;
        g_woh[idx] = __float2half(o < 27 ? wo[o * CK + c * KK + t] : 0.f);
    }
}

#define CSTRH 72

// ---------------------------------------------------------------------------
// Kernel B: offset conv via tensor cores.
// CTA = 128 px (one image row) x 32 out-ch, 256 threads = 8 warps.
// Per tap: im2col copy (coalesced uint4 from g_xth, zero-pad OOB) + MMA.
// Epilogue: py/px/sigmoid transform, planar coalesced writes to g_off.
// ---------------------------------------------------------------------------
__global__ void __launch_bounds__(256, 3) k_offcv(const float* __restrict__ b_off) {
    extern __shared__ __half smh[];
    __half* col = smh;                    // 128 * 72 halves
    __half* wsO = smh + 128 * CSTRH;      // 32 * 72 halves

    int tid = threadIdx.x;
    int b   = blockIdx.y;
    int p0  = blockIdx.x * 128;
    int ho  = blockIdx.x;                 // TP == WW == 128

    int g = tid >> 3, lane8 = tid & 7, cbase = lane8 * 8;
    const __half* xb = g_xth + (size_t)b * HW * CC;

    int lane = tid & 31, w = tid >> 5;
    int cobase = (w & 1) * 16;
    int pxh    = (w >> 1) * 32;
    int gid = lane >> 2, tig = lane & 3;

    float bl = (cobase + gid     < 27) ? b_off[cobase + gid]     : 0.f;
    float bh = (cobase + gid + 8 < 27) ? b_off[cobase + gid + 8] : 0.f;
    float acc[4][4];
    #pragma unroll
    for (int nt = 0; nt < 4; nt++) {
        acc[nt][0] = bl; acc[nt][1] = bl;
        acc[nt][2] = bh; acc[nt][3] = bh;
    }

    #pragma unroll 1
    for (int t = 0; t < 9; t++) {
        // stage tap-t offset weights
        const u32* wsrc = (const u32*)(g_woh + t * 32 * CC);
        #pragma unroll
        for (int idx = tid; idx < 1024; idx += 256) {
            int o = idx >> 5, kp = idx & 31;
            *(u32*)&wsO[o * CSTRH + kp * 2] = wsrc[idx];
        }

        // im2col for tap t (zero padding at borders)
        int dty = t / 3 - 1, dtx = t % 3 - 1;
        int y = ho + dty;
        bool vy = (y >= 0) & (y < HH);
        #pragma unroll
        for (int pass = 0; pass < 4; pass++) {
            int pi = pass * 32 + g;       // = wo since CTA covers one row
            int xx = pi + dtx;
            uint4 v = make_uint4(0, 0, 0, 0);
            if (vy & (xx >= 0) & (xx < WW))
                v = *(const uint4*)(xb + ((size_t)(y * WW + xx)) * CC + cbase);
            *(uint4*)&col[pi * CSTRH + cbase] = v;
        }
        __syncthreads();

        // MMA over this tap's k=64
        #pragma unroll
        for (int ks = 0; ks < 4; ks++) {
            int kb = ks * 16 + 2 * tig;
            u32 a0 = *(u32*)&wsO[(cobase + gid)     * CSTRH + kb];
            u32 a1 = *(u32*)&wsO[(cobase + gid + 8) * CSTRH + kb];
            u32 a2 = *(u32*)&wsO[(cobase + gid)     * CSTRH + kb + 8];
            u32 a3 = *(u32*)&wsO[(cobase + gid + 8) * CSTRH + kb + 8];
            #pragma unroll
            for (int nt = 0; nt < 4; nt++) {
                const __half* brow = &col[(pxh + nt * 8 + gid) * CSTRH + kb];
                u32 b0 = *(const u32*)brow;
                u32 b1 = *(const u32*)(brow + 8);
                asm volatile(
                    "mma.sync.aligned.m16n8k16.row.col.f32.f16.f16.f32 "
                    "{%0,%1,%2,%3}, {%4,%5,%6,%7}, {%8,%9}, {%0,%1,%2,%3};"
                    : "+f"(acc[nt][0]), "+f"(acc[nt][1]),
                      "+f"(acc[nt][2]), "+f"(acc[nt][3])
                    : "r"(a0), "r"(a1), "r"(a2), "r"(a3), "r"(b0), "r"(b1));
            }
        }
        __syncthreads();
    }

    // epilogue: transform + planar write
    float* ob = g_off + (size_t)b * 27 * HW;
    #pragma unroll
    for (int nt = 0; nt < 4; nt++) {
        int wo_lo = pxh + nt * 8 + 2 * tig;
        int p = p0 + wo_lo;
        #pragma unroll
        for (int j = 0; j < 2; j++) {
            int o = cobase + gid + j * 8;
            if (o >= 27) continue;
            float v0 = acc[nt][j * 2], v1 = acc[nt][j * 2 + 1];
            if (o < 9) {
                float a = (float)(ho + o / 3 - 1);
                v0 += a; v1 += a;
            } else if (o < 18) {
                int tt = o - 9;
                float a = (float)(wo_lo + tt % 3 - 1);
                v0 += a; v1 += a + 1.f;
            } else {
                v0 = 1.f / (1.f + __expf(-v0));
                v1 = 1.f / (1.f + __expf(-v1));
            }
            *(float2*)(ob + (size_t)o * HW + p) = make_float2(v0, v1);
        }
    }
}

// ---------------------------------------------------------------------------
// Kernel C: per-tap fused gather (fp32 -> fp16 col) + tensor-core GEMM.
// ---------------------------------------------------------------------------
#define TP 128

__global__ void __launch_bounds__(256, 3) k_dcn(const float* __restrict__ b_dcn,
                                                float* __restrict__ out) {
    extern __shared__ __half smh[];
    __half* col = smh;                    // TP * CSTRH
    __half* wsT = smh + TP * CSTRH;       // 64 * CSTRH

    int tid = threadIdx.x;
    int b   = blockIdx.y;
    int p0  = blockIdx.x * TP;

    int g = tid >> 3, lane8 = tid & 7, cbase = lane8 * 8;
    const float* xb = g_xt + (size_t)b * HW * CC;
    const float* offb = g_off + (size_t)b * 27 * HW;

    int lane = tid & 31, w = tid >> 5;
    int cobase = (w & 3) * 16;
    int pxh    = (w >> 2) * 64;
    int gid = lane >> 2, tig = lane & 3;

    float acc[8][4];
    #pragma unroll
    for (int i = 0; i < 8; i++)
        #pragma unroll
        for (int j = 0; j < 4; j++) acc[i][j] = 0.f;

    #pragma unroll 1
    for (int t = 0; t < 9; t++) {
        const u32* wsrc = (const u32*)(g_wth + t * CO * CC);
        #pragma unroll
        for (int idx = tid; idx < 2048; idx += 256) {
            int co = idx >> 5, kp = idx & 31;
            *(u32*)&wsT[co * CSTRH + kp * 2] = wsrc[co * 32 + kp];
        }

        #pragma unroll
        for (int pass = 0; pass < 4; pass++) {
            int pi = pass * 32 + g;
            int p  = p0 + pi;
            float py  = offb[(size_t)t * HW + p];
            float pxs = offb[(size_t)(9 + t) * HW + p];
            float mm  = offb[(size_t)(18 + t) * HW + p];
            float y0f = floorf(py), x0f = floorf(pxs);
            float dy = py - y0f, dx = pxs - x0f;
            int y0 = (int)y0f, x0 = (int)x0f;
            int y1 = y0 + 1,  x1 = x0 + 1;
            bool vy0 = (y0 >= 0) & (y0 < HH);
            bool vy1 = (y1 >= 0) & (y1 < HH);
            bool vx0 = (x0 >= 0) & (x0 < WW);
            bool vx1 = (x1 >= 0) & (x1 < WW);
            float w00 = (1.f - dy) * (1.f - dx) * mm;
            float w01 = (1.f - dy) * dx * mm;
            float w10 = dy * (1.f - dx) * mm;
            float w11 = dy * dx * mm;

            float r[8];
            #pragma unroll
            for (int j = 0; j < 8; j++) r[j] = 0.f;

            if (vy0 & vx0) {
                const float4* pp = (const float4*)(xb + ((size_t)(y0 * WW + x0)) * CC + cbase);
                float4 v = pp[0];
                r[0] += w00*v.x; r[1] += w00*v.y; r[2] += w00*v.z; r[3] += w00*v.w;
                v = pp[1];
                r[4] += w00*v.x; r[5] += w00*v.y; r[6] += w00*v.z; r[7] += w00*v.w;
            }
            if (vy0 & vx1) {
                const float4* pp = (const float4*)(xb + ((size_t)(y0 * WW + x1)) * CC + cbase);
                float4 v = pp[0];
                r[0] += w01*v.x; r[1] += w01*v.y; r[2] += w01*v.z; r[3] += w01*v.w;
                v = pp[1];
                r[4] += w01*v.x; r[5] += w01*v.y; r[6] += w01*v.z; r[7] += w01*v.w;
            }
            if (vy1 & vx0) {
                const float4* pp = (const float4*)(xb + ((size_t)(y1 * WW + x0)) * CC + cbase);
                float4 v = pp[0];
                r[0] += w10*v.x; r[1] += w10*v.y; r[2] += w10*v.z; r[3] += w10*v.w;
                v = pp[1];
                r[4] += w10*v.x; r[5] += w10*v.y; r[6] += w10*v.z; r[7] += w10*v.w;
            }
            if (vy1 & vx1) {
                const float4* pp = (const float4*)(xb + ((size_t)(y1 * WW + x1)) * CC + cbase);
                float4 v = pp[0];
                r[0] += w11*v.x; r[1] += w11*v.y; r[2] += w11*v.z; r[3] += w11*v.w;
                v = pp[1];
                r[4] += w11*v.x; r[5] += w11*v.y; r[6] += w11*v.z; r[7] += w11*v.w;
            }

            __half2 h0 = __floats2half2_rn(r[0], r[1]);
            __half2 h1 = __floats2half2_rn(r[2], r[3]);
            __half2 h2 = __floats2half2_rn(r[4], r[5]);
            __half2 h3 = __floats2half2_rn(r[6], r[7]);
            uint4 pack = make_uint4(*(u32*)&h0, *(u32*)&h1, *(u32*)&h2, *(u32*)&h3);
            *(uint4*)&col[pi * CSTRH + cbase] = pack;
        }
        __syncthreads();

        #pragma unroll
        for (int ks = 0; ks < 4; ks++) {
            int kb = ks * 16 + 2 * tig;
            u32 a0 = *(u32*)&wsT[(cobase + gid)     * CSTRH + kb];
            u32 a1 = *(u32*)&wsT[(cobase + gid + 8) * CSTRH + kb];
            u32 a2 = *(u32*)&wsT[(cobase + gid)     * CSTRH + kb + 8];
            u32 a3 = *(u32*)&wsT[(cobase + gid + 8) * CSTRH + kb + 8];
            #pragma unroll
            for (int nt = 0; nt < 8; nt++) {
                const __half* brow = &col[(pxh + nt * 8 + gid) * CSTRH + kb];
                u32 b0 = *(const u32*)brow;
                u32 b1 = *(const u32*)(brow + 8);
                asm volatile(
                    "mma.sync.aligned.m16n8k16.row.col.f32.f16.f16.f32 "
                    "{%0,%1,%2,%3}, {%4,%5,%6,%7}, {%8,%9}, {%0,%1,%2,%3};"
                    : "+f"(acc[nt][0]), "+f"(acc[nt][1]),
                      "+f"(acc[nt][2]), "+f"(acc[nt][3])
                    : "r"(a0), "r"(a1), "r"(a2), "r"(a3), "r"(b0), "r"(b1));
            }
        }
        __syncthreads();
    }

    float bl = b_dcn[cobase + gid];
    float bh = b_dcn[cobase + gid + 8];
    float* ob = out + (size_t)b * CO * HW + p0 + pxh + 2 * tig;
    #pragma unroll
    for (int nt = 0; nt < 8; nt++) {
        float2 vlo = make_float2(acc[nt][0] + bl, acc[nt][1] + bl);
        float2 vhi = make_float2(acc[nt][2] + bh, acc[nt][3] + bh);
        *(float2*)(ob + (size_t)(cobase + gid)     * HW + nt * 8) = vlo;
        *(float2*)(ob + (size_t)(cobase + gid + 8) * HW + nt * 8) = vhi;
    }
}

// ---------------------------------------------------------------------------
extern "C" void kernel_launch(void* const* d_in, const int* in_sizes, int n_in,
                              void* d_out, int out_size) {
    const float* x        = (const float*)d_in[0];
    const float* w_offset = (const float*)d_in[1];
    const float* b_offset = (const float*)d_in[2];
    const float* w_dcn    = (const float*)d_in[3];
    const float* b_dcn    = (const float*)d_in[4];
    float* out = (float*)d_out;

    const int SMEM_O = (128 * CSTRH + 32 * CSTRH) * 2;   // 23040
    const int SMEM_C = (TP  * CSTRH + CO * CSTRH) * 2;   // 27648
    cudaFuncSetAttribute(k_offcv, cudaFuncAttributeMaxDynamicSharedMemorySize, SMEM_O);
    cudaFuncSetAttribute(k_dcn,   cudaFuncAttributeMaxDynamicSharedMemorySize, SMEM_C);

    k_transpose<<<dim3(HW / 32, CC / 32, BB), dim3(32, 8)>>>(x);
    k_wreorder<<<(KK * CO * CC + 255) / 256, 256>>>(w_dcn, w_offset);
    k_offcv<<<dim3(HW / 128, BB), 256, SMEM_O>>>(b_offset);
    k_dcn<<<dim3(HW / TP, BB), 256, SMEM_C>>>(b_dcn, out);
}

// round 6
// speedup vs baseline: 7.9086x; 1.1374x over previous
#include <cuda_runtime.h>
#include <cuda_fp16.h>
#include <math.h>

#define BB 8
#define CC 64
#define HH 128
#define WW 128
#define HW (HH*WW)
#define KK 9
#define CO 64
#define CK (CC*KK)   // 576

typedef unsigned int u32;

__device__ __half g_xth[BB*HW*CC];      // x NHWC fp16 (both convs' source)
__device__ float  g_off[BB*27*HW];      // planar: [b][plane][HW]
__device__ __half g_wth[KK*CO*CC];      // dcn weights [t][co][c] fp16
__device__ __half g_woh[KK*32*CC];      // offset weights [t][o pad32][c] fp16

// ---------------------------------------------------------------------------
// Kernel A: NCHW -> NHWC transpose (fp16 output)
// ---------------------------------------------------------------------------
__global__ void k_transpose(const float* __restrict__ x) {
    __shared__ float tile[32][33];
    int b  = blockIdx.z;
    int p0 = blockIdx.x * 32;
    int c0 = blockIdx.y * 32;
    int tx = threadIdx.x, ty = threadIdx.y;   // 32 x 8
    const float* xb = x + (size_t)b * CC * HW;
    #pragma unroll
    for (int i = 0; i < 32; i += 8)
        tile[ty + i][tx] = xb[(size_t)(c0 + ty + i) * HW + p0 + tx];
    __syncthreads();
    __half* xoh = g_xth + (size_t)b * HW * CC;
    #pragma unroll
    for (int i = 0; i < 32; i += 8)
        xoh[(size_t)(p0 + ty + i) * CC + c0 + tx] = __float2half(tile[tx][ty + i]);
}

// ---------------------------------------------------------------------------
// Kernel W: weight reorder/convert for both GEMMs
// ---------------------------------------------------------------------------
__global__ void k_wreorder(const float* __restrict__ wd, const float* __restrict__ wo) {
    int idx = blockIdx.x * 256 + threadIdx.x;
    if (idx < KK * CO * CC) {                 // dcn: [t][co][c]
        int t  = idx >> 12;
        int co = (idx >> 6) & 63;
        int c  = idx & 63;
        g_wth[idx] = __float2half(wd[co * CK + c * KK + t]);
    }
    if (idx < KK * 32 * CC) {                 // offset: [t][o pad32][c]
        int t = idx >> 11;
        int o = (idx >> 6) & 31;
        int c = idx & 63;
        g_woh[idx] = __float2half(o < 27 ? wo[o * CK + c * KK + t] : 0.f);
    }
}

#define CSTRH 72

// ---------------------------------------------------------------------------
// Kernel B: offset conv via tensor cores (unchanged from R5)
// ---------------------------------------------------------------------------
__global__ void __launch_bounds__(256, 3) k_offcv(const float* __restrict__ b_off) {
    extern __shared__ __half smh[];
    __half* col = smh;                    // 128 * 72 halves
    __half* wsO = smh + 128 * CSTRH;      // 32 * 72 halves

    int tid = threadIdx.x;
    int b   = blockIdx.y;
    int p0  = blockIdx.x * 128;
    int ho  = blockIdx.x;

    int g = tid >> 3, lane8 = tid & 7, cbase = lane8 * 8;
    const __half* xb = g_xth + (size_t)b * HW * CC;

    int lane = tid & 31, w = tid >> 5;
    int cobase = (w & 1) * 16;
    int pxh    = (w >> 1) * 32;
    int gid = lane >> 2, tig = lane & 3;

    float bl = (cobase + gid     < 27) ? b_off[cobase + gid]     : 0.f;
    float bh = (cobase + gid + 8 < 27) ? b_off[cobase + gid + 8] : 0.f;
    float acc[4][4];
    #pragma unroll
    for (int nt = 0; nt < 4; nt++) {
        acc[nt][0] = bl; acc[nt][1] = bl;
        acc[nt][2] = bh; acc[nt][3] = bh;
    }

    #pragma unroll 1
    for (int t = 0; t < 9; t++) {
        const u32* wsrc = (const u32*)(g_woh + t * 32 * CC);
        #pragma unroll
        for (int idx = tid; idx < 1024; idx += 256) {
            int o = idx >> 5, kp = idx & 31;
            *(u32*)&wsO[o * CSTRH + kp * 2] = wsrc[idx];
        }

        int dty = t / 3 - 1, dtx = t % 3 - 1;
        int y = ho + dty;
        bool vy = (y >= 0) & (y < HH);
        #pragma unroll
        for (int pass = 0; pass < 4; pass++) {
            int pi = pass * 32 + g;
            int xx = pi + dtx;
            uint4 v = make_uint4(0, 0, 0, 0);
            if (vy & (xx >= 0) & (xx < WW))
                v = *(const uint4*)(xb + ((size_t)(y * WW + xx)) * CC + cbase);
            *(uint4*)&col[pi * CSTRH + cbase] = v;
        }
        __syncthreads();

        #pragma unroll
        for (int ks = 0; ks < 4; ks++) {
            int kb = ks * 16 + 2 * tig;
            u32 a0 = *(u32*)&wsO[(cobase + gid)     * CSTRH + kb];
            u32 a1 = *(u32*)&wsO[(cobase + gid + 8) * CSTRH + kb];
            u32 a2 = *(u32*)&wsO[(cobase + gid)     * CSTRH + kb + 8];
            u32 a3 = *(u32*)&wsO[(cobase + gid + 8) * CSTRH + kb + 8];
            #pragma unroll
            for (int nt = 0; nt < 4; nt++) {
                const __half* brow = &col[(pxh + nt * 8 + gid) * CSTRH + kb];
                u32 b0 = *(const u32*)brow;
                u32 b1 = *(const u32*)(brow + 8);
                asm volatile(
                    "mma.sync.aligned.m16n8k16.row.col.f32.f16.f16.f32 "
                    "{%0,%1,%2,%3}, {%4,%5,%6,%7}, {%8,%9}, {%0,%1,%2,%3};"
                    : "+f"(acc[nt][0]), "+f"(acc[nt][1]),
                      "+f"(acc[nt][2]), "+f"(acc[nt][3])
                    : "r"(a0), "r"(a1), "r"(a2), "r"(a3), "r"(b0), "r"(b1));
            }
        }
        __syncthreads();
    }

    float* ob = g_off + (size_t)b * 27 * HW;
    #pragma unroll
    for (int nt = 0; nt < 4; nt++) {
        int wo_lo = pxh + nt * 8 + 2 * tig;
        int p = p0 + wo_lo;
        #pragma unroll
        for (int j = 0; j < 2; j++) {
            int o = cobase + gid + j * 8;
            if (o >= 27) continue;
            float v0 = acc[nt][j * 2], v1 = acc[nt][j * 2 + 1];
            if (o < 9) {
                float a = (float)(ho + o / 3 - 1);
                v0 += a; v1 += a;
            } else if (o < 18) {
                int tt = o - 9;
                float a = (float)(wo_lo + tt % 3 - 1);
                v0 += a; v1 += a + 1.f;
            } else {
                v0 = 1.f / (1.f + __expf(-v0));
                v1 = 1.f / (1.f + __expf(-v1));
            }
            *(float2*)(ob + (size_t)o * HW + p) = make_float2(v0, v1);
        }
    }
}

// ---------------------------------------------------------------------------
// Kernel C: per-tap fused gather (fp16 loads, fp32 combine) + tensor-core GEMM
// ---------------------------------------------------------------------------
#define TP 128

__global__ void __launch_bounds__(256, 3) k_dcn(const float* __restrict__ b_dcn,
                                                float* __restrict__ out) {
    extern __shared__ __half smh[];
    __half* col = smh;                    // TP * CSTRH
    __half* wsT = smh + TP * CSTRH;       // 64 * CSTRH

    int tid = threadIdx.x;
    int b   = blockIdx.y;
    int p0  = blockIdx.x * TP;

    int g = tid >> 3, lane8 = tid & 7, cbase = lane8 * 8;
    const __half* xb = g_xth + (size_t)b * HW * CC;
    const float* offb = g_off + (size_t)b * 27 * HW;

    int lane = tid & 31, w = tid >> 5;
    int cobase = (w & 3) * 16;
    int pxh    = (w >> 2) * 64;
    int gid = lane >> 2, tig = lane & 3;

    float acc[8][4];
    #pragma unroll
    for (int i = 0; i < 8; i++)
        #pragma unroll
        for (int j = 0; j < 4; j++) acc[i][j] = 0.f;

    #pragma unroll 1
    for (int t = 0; t < 9; t++) {
        const u32* wsrc = (const u32*)(g_wth + t * CO * CC);
        #pragma unroll
        for (int idx = tid; idx < 2048; idx += 256) {
            int co = idx >> 5, kp = idx & 31;
            *(u32*)&wsT[co * CSTRH + kp * 2] = wsrc[co * 32 + kp];
        }

        #pragma unroll
        for (int pass = 0; pass < 4; pass++) {
            int pi = pass * 32 + g;
            int p  = p0 + pi;
            float py  = offb[(size_t)t * HW + p];
            float pxs = offb[(size_t)(9 + t) * HW + p];
            float mm  = offb[(size_t)(18 + t) * HW + p];
            float y0f = floorf(py), x0f = floorf(pxs);
            float dy = py - y0f, dx = pxs - x0f;
            int y0 = (int)y0f, x0 = (int)x0f;
            int y1 = y0 + 1,  x1 = x0 + 1;
            bool vy0 = (y0 >= 0) & (y0 < HH);
            bool vy1 = (y1 >= 0) & (y1 < HH);
            bool vx0 = (x0 >= 0) & (x0 < WW);
            bool vx1 = (x1 >= 0) & (x1 < WW);
            float w00 = (1.f - dy) * (1.f - dx) * mm;
            float w01 = (1.f - dy) * dx * mm;
            float w10 = dy * (1.f - dx) * mm;
            float w11 = dy * dx * mm;

            float r[8];
            #pragma unroll
            for (int j = 0; j < 8; j++) r[j] = 0.f;

            // each corner: one LDG.128 = 8 fp16 channels; convert + fp32 fma
            #define CORNER(valid, yy, xx, wgt)                                          \
                if (valid) {                                                            \
                    uint4 v = *(const uint4*)(xb + ((size_t)((yy) * WW + (xx))) * CC + cbase); \
                    const __half2* hp = (const __half2*)&v;                             \
                    float2 f;                                                           \
                    f = __half22float2(hp[0]); r[0] += wgt * f.x; r[1] += wgt * f.y;    \
                    f = __half22float2(hp[1]); r[2] += wgt * f.x; r[3] += wgt * f.y;    \
                    f = __half22float2(hp[2]); r[4] += wgt * f.x; r[5] += wgt * f.y;    \
                    f = __half22float2(hp[3]); r[6] += wgt * f.x; r[7] += wgt * f.y;    \
                }

            CORNER(vy0 & vx0, y0, x0, w00)
            CORNER(vy0 & vx1, y0, x1, w01)
            CORNER(vy1 & vx0, y1, x0, w10)
            CORNER(vy1 & vx1, y1, x1, w11)
            #undef CORNER

            __half2 h0 = __floats2half2_rn(r[0], r[1]);
            __half2 h1 = __floats2half2_rn(r[2], r[3]);
            __half2 h2 = __floats2half2_rn(r[4], r[5]);
            __half2 h3 = __floats2half2_rn(r[6], r[7]);
            uint4 pack = make_uint4(*(u32*)&h0, *(u32*)&h1, *(u32*)&h2, *(u32*)&h3);
            *(uint4*)&col[pi * CSTRH + cbase] = pack;
        }
        __syncthreads();

        #pragma unroll
        for (int ks = 0; ks < 4; ks++) {
            int kb = ks * 16 + 2 * tig;
            u32 a0 = *(u32*)&wsT[(cobase + gid)     * CSTRH + kb];
            u32 a1 = *(u32*)&wsT[(cobase + gid + 8) * CSTRH + kb];
            u32 a2 = *(u32*)&wsT[(cobase + gid)     * CSTRH + kb + 8];
            u32 a3 = *(u32*)&wsT[(cobase + gid + 8) * CSTRH + kb + 8];
            #pragma unroll
            for (int nt = 0; nt < 8; nt++) {
                const __half* brow = &col[(pxh + nt * 8 + gid) * CSTRH + kb];
                u32 b0 = *(const u32*)brow;
                u32 b1 = *(const u32*)(brow + 8);
                asm volatile(
                    "mma.sync.aligned.m16n8k16.row.col.f32.f16.f16.f32 "
                    "{%0,%1,%2,%3}, {%4,%5,%6,%7}, {%8,%9}, {%0,%1,%2,%3};"
                    : "+f"(acc[nt][0]), "+f"(acc[nt][1]),
                      "+f"(acc[nt][2]), "+f"(acc[nt][3])
                    : "r"(a0), "r"(a1), "r"(a2), "r"(a3), "r"(b0), "r"(b1));
            }
        }
        __syncthreads();
    }

    float bl = b_dcn[cobase + gid];
    float bh = b_dcn[cobase + gid + 8];
    float* ob = out + (size_t)b * CO * HW + p0 + pxh + 2 * tig;
    #pragma unroll
    for (int nt = 0; nt < 8; nt++) {
        float2 vlo = make_float2(acc[nt][0] + bl, acc[nt][1] + bl);
        float2 vhi = make_float2(acc[nt][2] + bh, acc[nt][3] + bh);
        *(float2*)(ob + (size_t)(cobase + gid)     * HW + nt * 8) = vlo;
        *(float2*)(ob + (size_t)(cobase + gid + 8) * HW + nt * 8) = vhi;
    }
}

// ---------------------------------------------------------------------------
extern "C" void kernel_launch(void* const* d_in, const int* in_sizes, int n_in,
                              void* d_out, int out_size) {
    const float* x        = (const float*)d_in[0];
    const float* w_offset = (const float*)d_in[1];
    const float* b_offset = (const float*)d_in[2];
    const float* w_dcn    = (const float*)d_in[3];
    const float* b_dcn    = (const float*)d_in[4];
    float* out = (float*)d_out;

    const int SMEM_O = (128 * CSTRH + 32 * CSTRH) * 2;   // 23040
    const int SMEM_C = (TP  * CSTRH + CO * CSTRH) * 2;   // 27648
    cudaFuncSetAttribute(k_offcv, cudaFuncAttributeMaxDynamicSharedMemorySize, SMEM_O);
    cudaFuncSetAttribute(k_dcn,   cudaFuncAttributeMaxDynamicSharedMemorySize, SMEM_C);

    k_transpose<<<dim3(HW / 32, CC / 32, BB), dim3(32, 8)>>>(x);
    k_wreorder<<<(KK * CO * CC + 255) / 256, 256>>>(w_dcn, w_offset);
    k_offcv<<<dim3(HW / 128, BB), 256, SMEM_O>>>(b_offset);
    k_dcn<<<dim3(HW / TP, BB), 256, SMEM_C>>>(b_dcn, out);
}

// round 7
// speedup vs baseline: 8.2201x; 1.0394x over previous
#include <cuda_runtime.h>
#include <cuda_fp16.h>
#include <math.h>

#define BB 8
#define CC 64
#define HH 128
#define WW 128
#define HW (HH*WW)
#define KK 9
#define CO 64
#define CK (CC*KK)   // 576

typedef unsigned int u32;

__device__ __half g_xth[BB*HW*CC];      // x NHWC fp16
__device__ float  g_off[BB*27*HW];      // planar offsets/masks
__device__ __half g_wth[KK*CO*CC];      // dcn weights [t][co][c] fp16
__device__ __half g_woh[KK*32*CC];      // offset weights [t][o pad32][c] fp16

#define CSTRH 72
#define TP 128

// ---------------------------------------------------------------------------
// Kernel A: NCHW -> NHWC transpose (fp16 output)
// ---------------------------------------------------------------------------
__global__ void k_transpose(const float* __restrict__ x) {
    __shared__ float tile[32][33];
    int b  = blockIdx.z;
    int p0 = blockIdx.x * 32;
    int c0 = blockIdx.y * 32;
    int tx = threadIdx.x, ty = threadIdx.y;   // 32 x 8
    const float* xb = x + (size_t)b * CC * HW;
    #pragma unroll
    for (int i = 0; i < 32; i += 8)
        tile[ty + i][tx] = xb[(size_t)(c0 + ty + i) * HW + p0 + tx];
    __syncthreads();
    __half* xoh = g_xth + (size_t)b * HW * CC;
    #pragma unroll
    for (int i = 0; i < 32; i += 8)
        xoh[(size_t)(p0 + ty + i) * CC + c0 + tx] = __float2half(tile[tx][ty + i]);
}

// ---------------------------------------------------------------------------
// Kernel W: weight reorder/convert
// ---------------------------------------------------------------------------
__global__ void k_wreorder(const float* __restrict__ wd, const float* __restrict__ wo) {
    int idx = blockIdx.x * 256 + threadIdx.x;
    if (idx < KK * CO * CC) {
        int t  = idx >> 12;
        int co = (idx >> 6) & 63;
        int c  = idx & 63;
        g_wth[idx] = __float2half(wd[co * CK + c * KK + t]);
    }
    if (idx < KK * 32 * CC) {
        int t = idx >> 11;
        int o = (idx >> 6) & 31;
        int c = idx & 63;
        g_woh[idx] = __float2half(o < 27 ? wo[o * CK + c * KK + t] : 0.f);
    }
}

// ---------------------------------------------------------------------------
// Kernel B: offset conv via tensor cores (as R6)
// ---------------------------------------------------------------------------
__global__ void __launch_bounds__(256, 3) k_offcv(const float* __restrict__ b_off) {
    extern __shared__ __half smh[];
    __half* col = smh;                    // 128 * 72 halves
    __half* wsO = smh + 128 * CSTRH;      // 32 * 72 halves

    int tid = threadIdx.x;
    int b   = blockIdx.y;
    int p0  = blockIdx.x * 128;
    int ho  = blockIdx.x;

    int g = tid >> 3, lane8 = tid & 7, cbase = lane8 * 8;
    const __half* xb = g_xth + (size_t)b * HW * CC;

    int lane = tid & 31, w = tid >> 5;
    int cobase = (w & 1) * 16;
    int pxh    = (w >> 1) * 32;
    int gid = lane >> 2, tig = lane & 3;

    float bl = (cobase + gid     < 27) ? b_off[cobase + gid]     : 0.f;
    float bh = (cobase + gid + 8 < 27) ? b_off[cobase + gid + 8] : 0.f;
    float acc[4][4];
    #pragma unroll
    for (int nt = 0; nt < 4; nt++) {
        acc[nt][0] = bl; acc[nt][1] = bl;
        acc[nt][2] = bh; acc[nt][3] = bh;
    }

    #pragma unroll 1
    for (int t = 0; t < 9; t++) {
        const u32* wsrc = (const u32*)(g_woh + t * 32 * CC);
        #pragma unroll
        for (int idx = tid; idx < 1024; idx += 256) {
            int o = idx >> 5, kp = idx & 31;
            *(u32*)&wsO[o * CSTRH + kp * 2] = wsrc[idx];
        }

        int dty = t / 3 - 1, dtx = t % 3 - 1;
        int y = ho + dty;
        bool vy = (y >= 0) & (y < HH);
        #pragma unroll
        for (int pass = 0; pass < 4; pass++) {
            int pi = pass * 32 + g;
            int xx = pi + dtx;
            uint4 v = make_uint4(0, 0, 0, 0);
            if (vy & (xx >= 0) & (xx < WW))
                v = *(const uint4*)(xb + ((size_t)(y * WW + xx)) * CC + cbase);
            *(uint4*)&col[pi * CSTRH + cbase] = v;
        }
        __syncthreads();

        #pragma unroll
        for (int ks = 0; ks < 4; ks++) {
            int kb = ks * 16 + 2 * tig;
            u32 a0 = *(u32*)&wsO[(cobase + gid)     * CSTRH + kb];
            u32 a1 = *(u32*)&wsO[(cobase + gid + 8) * CSTRH + kb];
            u32 a2 = *(u32*)&wsO[(cobase + gid)     * CSTRH + kb + 8];
            u32 a3 = *(u32*)&wsO[(cobase + gid + 8) * CSTRH + kb + 8];
            #pragma unroll
            for (int nt = 0; nt < 4; nt++) {
                const __half* brow = &col[(pxh + nt * 8 + gid) * CSTRH + kb];
                u32 b0 = *(const u32*)brow;
                u32 b1 = *(const u32*)(brow + 8);
                asm volatile(
                    "mma.sync.aligned.m16n8k16.row.col.f32.f16.f16.f32 "
                    "{%0,%1,%2,%3}, {%4,%5,%6,%7}, {%8,%9}, {%0,%1,%2,%3};"
                    : "+f"(acc[nt][0]), "+f"(acc[nt][1]),
                      "+f"(acc[nt][2]), "+f"(acc[nt][3])
                    : "r"(a0), "r"(a1), "r"(a2), "r"(a3), "r"(b0), "r"(b1));
            }
        }
        __syncthreads();
    }

    float* ob = g_off + (size_t)b * 27 * HW;
    #pragma unroll
    for (int nt = 0; nt < 4; nt++) {
        int wo_lo = pxh + nt * 8 + 2 * tig;
        int p = p0 + wo_lo;
        #pragma unroll
        for (int j = 0; j < 2; j++) {
            int o = cobase + gid + j * 8;
            if (o >= 27) continue;
            float v0 = acc[nt][j * 2], v1 = acc[nt][j * 2 + 1];
            if (o < 9) {
                float a = (float)(ho + o / 3 - 1);
                v0 += a; v1 += a;
            } else if (o < 18) {
                int tt = o - 9;
                float a = (float)(wo_lo + tt % 3 - 1);
                v0 += a; v1 += a + 1.f;
            } else {
                v0 = 1.f / (1.f + __expf(-v0));
                v1 = 1.f / (1.f + __expf(-v1));
            }
            *(float2*)(ob + (size_t)o * HW + p) = make_float2(v0, v1);
        }
    }
}

// ---------------------------------------------------------------------------
// k_dcn helpers
// ---------------------------------------------------------------------------
__device__ __forceinline__ void stage_w(__half* __restrict__ wbuf, int t, int tid) {
    const u32* wsrc = (const u32*)(g_wth + t * CO * CC);
    #pragma unroll
    for (int idx = tid; idx < 2048; idx += 256) {
        int co = idx >> 5, kp = idx & 31;
        *(u32*)&wbuf[co * CSTRH + kp * 2] = wsrc[idx];
    }
}

// branch-free bilinear gather of one tap into cbuf (128 px x 64 ch)
__device__ __forceinline__ void gather_tap(const __half* __restrict__ xb,
                                           const float* __restrict__ offb,
                                           __half* __restrict__ cbuf,
                                           int t, int p0, int g, int cbase) {
    #pragma unroll
    for (int pass = 0; pass < 4; pass++) {
        int pi = pass * 32 + g;
        int p  = p0 + pi;
        float py  = offb[(size_t)t * HW + p];
        float pxs = offb[(size_t)(9 + t) * HW + p];
        float mm  = offb[(size_t)(18 + t) * HW + p];
        float y0f = floorf(py), x0f = floorf(pxs);
        float dy = py - y0f, dx = pxs - x0f;
        int y0 = (int)y0f, x0 = (int)x0f;
        int y1 = y0 + 1,  x1 = x0 + 1;
        // fold per-corner validity into weights; clamp coords for safe loads
        float wy0 = ((y0 >= 0) & (y0 < HH)) ? (1.f - dy) * mm : 0.f;
        float wy1 = ((y1 >= 0) & (y1 < HH)) ? dy * mm : 0.f;
        float wx0 = ((x0 >= 0) & (x0 < WW)) ? (1.f - dx) : 0.f;
        float wx1 = ((x1 >= 0) & (x1 < WW)) ? dx : 0.f;
        float w00 = wy0 * wx0, w01 = wy0 * wx1;
        float w10 = wy1 * wx0, w11 = wy1 * wx1;
        int y0c = min(max(y0, 0), HH - 1), y1c = min(max(y1, 0), HH - 1);
        int x0c = min(max(x0, 0), WW - 1), x1c = min(max(x1, 0), WW - 1);

        uint4 v00 = *(const uint4*)(xb + ((size_t)(y0c * WW + x0c)) * CC + cbase);
        uint4 v01 = *(const uint4*)(xb + ((size_t)(y0c * WW + x1c)) * CC + cbase);
        uint4 v10 = *(const uint4*)(xb + ((size_t)(y1c * WW + x0c)) * CC + cbase);
        uint4 v11 = *(const uint4*)(xb + ((size_t)(y1c * WW + x1c)) * CC + cbase);
        const __half2* h00 = (const __half2*)&v00;
        const __half2* h01 = (const __half2*)&v01;
        const __half2* h10 = (const __half2*)&v10;
        const __half2* h11 = (const __half2*)&v11;

        __half2 hh[4];
        #pragma unroll
        for (int q = 0; q < 4; q++) {
            float2 f00 = __half22float2(h00[q]);
            float2 f01 = __half22float2(h01[q]);
            float2 f10 = __half22float2(h10[q]);
            float2 f11 = __half22float2(h11[q]);
            float rx = w00 * f00.x + w01 * f01.x + w10 * f10.x + w11 * f11.x;
            float ry = w00 * f00.y + w01 * f01.y + w10 * f10.y + w11 * f11.y;
            hh[q] = __floats2half2_rn(rx, ry);
        }
        *(uint4*)&cbuf[pi * CSTRH + cbase] = *(uint4*)hh;
    }
}

__device__ __forceinline__ void mma_tap(const __half* __restrict__ col,
                                        const __half* __restrict__ wsT,
                                        float (&acc)[8][4],
                                        int cobase, int pxh, int gid, int tig) {
    #pragma unroll
    for (int ks = 0; ks < 4; ks++) {
        int kb = ks * 16 + 2 * tig;
        u32 a0 = *(const u32*)&wsT[(cobase + gid)     * CSTRH + kb];
        u32 a1 = *(const u32*)&wsT[(cobase + gid + 8) * CSTRH + kb];
        u32 a2 = *(const u32*)&wsT[(cobase + gid)     * CSTRH + kb + 8];
        u32 a3 = *(const u32*)&wsT[(cobase + gid + 8) * CSTRH + kb + 8];
        #pragma unroll
        for (int nt = 0; nt < 8; nt++) {
            const __half* brow = &col[(pxh + nt * 8 + gid) * CSTRH + kb];
            u32 b0 = *(const u32*)brow;
            u32 b1 = *(const u32*)(brow + 8);
            asm volatile(
                "mma.sync.aligned.m16n8k16.row.col.f32.f16.f16.f32 "
                "{%0,%1,%2,%3}, {%4,%5,%6,%7}, {%8,%9}, {%0,%1,%2,%3};"
                : "+f"(acc[nt][0]), "+f"(acc[nt][1]),
                  "+f"(acc[nt][2]), "+f"(acc[nt][3])
                : "r"(a0), "r"(a1), "r"(a2), "r"(a3), "r"(b0), "r"(b1));
        }
    }
}

// ---------------------------------------------------------------------------
// Kernel C: software-pipelined gather + tensor-core GEMM (double-buffered)
// ---------------------------------------------------------------------------
__global__ void __launch_bounds__(256, 3) k_dcn(const float* __restrict__ b_dcn,
                                                float* __restrict__ out) {
    extern __shared__ __half smh[];
    __half* cb[2] = { smh, smh + TP * CSTRH };
    __half* wb[2] = { smh + 2 * TP * CSTRH, smh + 2 * TP * CSTRH + CO * CSTRH };

    int tid = threadIdx.x;
    int b   = blockIdx.y;
    int p0  = blockIdx.x * TP;

    int g = tid >> 3, lane8 = tid & 7, cbase = lane8 * 8;
    const __half* xb = g_xth + (size_t)b * HW * CC;
    const float* offb = g_off + (size_t)b * 27 * HW;

    int lane = tid & 31, w = tid >> 5;
    int cobase = (w & 3) * 16;
    int pxh    = (w >> 2) * 64;
    int gid = lane >> 2, tig = lane & 3;

    float acc[8][4];
    #pragma unroll
    for (int i = 0; i < 8; i++)
        #pragma unroll
        for (int j = 0; j < 4; j++) acc[i][j] = 0.f;

    // prologue: fill stage 0
    stage_w(wb[0], 0, tid);
    gather_tap(xb, offb, cb[0], 0, p0, g, cbase);
    __syncthreads();

    #pragma unroll 1
    for (int t = 0; t < 9; t++) {
        int cur = t & 1, nxt = cur ^ 1;
        if (t < 8) {
            stage_w(wb[nxt], t + 1, tid);                       // short L2 loads
            gather_tap(xb, offb, cb[nxt], t + 1, p0, g, cbase); // long LDGs in flight
        }
        mma_tap(cb[cur], wb[cur], acc, cobase, pxh, gid, tig);  // overlaps with loads
        __syncthreads();
    }

    float bl = b_dcn[cobase + gid];
    float bh = b_dcn[cobase + gid + 8];
    float* ob = out + (size_t)b * CO * HW + p0 + pxh + 2 * tig;
    #pragma unroll
    for (int nt = 0; nt < 8; nt++) {
        float2 vlo = make_float2(acc[nt][0] + bl, acc[nt][1] + bl);
        float2 vhi = make_float2(acc[nt][2] + bh, acc[nt][3] + bh);
        *(float2*)(ob + (size_t)(cobase + gid)     * HW + nt * 8) = vlo;
        *(float2*)(ob + (size_t)(cobase + gid + 8) * HW + nt * 8) = vhi;
    }
}

// ---------------------------------------------------------------------------
extern "C" void kernel_launch(void* const* d_in, const int* in_sizes, int n_in,
                              void* d_out, int out_size) {
    const float* x        = (const float*)d_in[0];
    const float* w_offset = (const float*)d_in[1];
    const float* b_offset = (const float*)d_in[2];
    const float* w_dcn    = (const float*)d_in[3];
    const float* b_dcn    = (const float*)d_in[4];
    float* out = (float*)d_out;

    const int SMEM_O = (128 * CSTRH + 32 * CSTRH) * 2;             // 23040
    const int SMEM_C = (2 * TP * CSTRH + 2 * CO * CSTRH) * 2;      // 55296
    cudaFuncSetAttribute(k_offcv, cudaFuncAttributeMaxDynamicSharedMemorySize, SMEM_O);
    cudaFuncSetAttribute(k_dcn,   cudaFuncAttributeMaxDynamicSharedMemorySize, SMEM_C);

    k_transpose<<<dim3(HW / 32, CC / 32, BB), dim3(32, 8)>>>(x);
    k_wreorder<<<(KK * CO * CC + 255) / 256, 256>>>(w_dcn, w_offset);
    k_offcv<<<dim3(HW / 128, BB), 256, SMEM_O>>>(b_offset);
    k_dcn<<<dim3(HW / TP, BB), 256, SMEM_C>>>(b_dcn, out);
}